// round 1
// baseline (speedup 1.0000x reference)
#include <cuda_runtime.h>

#define N_NODES 50000
#define N_EDGES 800000
#define N_EL    100000

// ---------------- scratch (device globals; no allocation allowed) ----------------
__device__ float g_deg [N_NODES];
__device__ float g_dinv[N_NODES];
__device__ float g_h1  [N_NODES * 64];
__device__ float g_z1  [N_NODES * 64];
__device__ float g_h2  [N_NODES * 64];
__device__ float g_z2  [N_NODES * 64];
__device__ float g_ef  [N_EL * 64];
__device__ float g_m1  [N_EL * 64];
__device__ float g_m2  [N_EL * 64];

// ---------------- degree / normalization ----------------
__global__ void zero_deg_kernel() {
    int i = blockIdx.x * 256 + threadIdx.x;
    if (i < N_NODES) g_deg[i] = 0.0f;
}

__global__ void count_deg_kernel(const int* __restrict__ dst) {
    int e = blockIdx.x * 256 + threadIdx.x;
    if (e < N_EDGES) atomicAdd(&g_deg[dst[e]], 1.0f);
}

__global__ void dinv_kernel() {
    int i = blockIdx.x * 256 + threadIdx.x;
    if (i < N_NODES) g_dinv[i] = rsqrtf(g_deg[i] + 1.0f);  // +1 = self-loop
}

// ---------------- tiled fp32 GEMM: C[M,64] = A[M,K] @ B[K,64] ----------------
// DUAL:  C = raw product, C2 = C * dinv[row]^2 (self-loop init for scatter target)
// !DUAL: C = act(prod + bias), RELU optional
template<int K, bool DUAL, bool RELU>
__launch_bounds__(256)
__global__ void gemm64_kernel(const float* __restrict__ A,
                              const float* __restrict__ B,
                              const float* __restrict__ bias,
                              float* __restrict__ C,
                              float* __restrict__ C2,
                              int M)
{
    __shared__ float As[64 * 68];   // [kk][row] transposed, pad 68 to dodge conflicts
    __shared__ float Bs[64 * 64];   // [kk][col]
    const int tid  = threadIdx.x;
    const int row0 = blockIdx.x * 64;
    const int ty   = tid >> 4;      // 0..15 -> 4 rows each
    const int tx   = tid & 15;      // 0..15 -> 4 cols each

    float acc[4][4] = {};

    for (int k0 = 0; k0 < K; k0 += 64) {
        // stage A chunk (64 rows x 64 k), transposed into As
        #pragma unroll
        for (int idx = tid; idx < 64 * 16; idx += 256) {
            int r = idx >> 4, kk4 = (idx & 15) << 2;
            int row = row0 + r;
            float4 av = (row < M) ? *(const float4*)&A[row * K + k0 + kk4]
                                  : make_float4(0.f, 0.f, 0.f, 0.f);
            As[(kk4 + 0) * 68 + r] = av.x;
            As[(kk4 + 1) * 68 + r] = av.y;
            As[(kk4 + 2) * 68 + r] = av.z;
            As[(kk4 + 3) * 68 + r] = av.w;
        }
        // stage B chunk (64 k x 64 cols)
        #pragma unroll
        for (int idx = tid; idx < 64 * 16; idx += 256)
            *(float4*)&Bs[idx << 2] = *(const float4*)&B[(k0 << 6) + (idx << 2)];
        __syncthreads();

        #pragma unroll 8
        for (int kk = 0; kk < 64; kk++) {
            float4 a = *(const float4*)&As[kk * 68 + (ty << 2)];
            float4 b = *(const float4*)&Bs[(kk << 6) + (tx << 2)];
            acc[0][0] += a.x * b.x; acc[0][1] += a.x * b.y; acc[0][2] += a.x * b.z; acc[0][3] += a.x * b.w;
            acc[1][0] += a.y * b.x; acc[1][1] += a.y * b.y; acc[1][2] += a.y * b.z; acc[1][3] += a.y * b.w;
            acc[2][0] += a.z * b.x; acc[2][1] += a.z * b.y; acc[2][2] += a.z * b.z; acc[2][3] += a.z * b.w;
            acc[3][0] += a.w * b.x; acc[3][1] += a.w * b.y; acc[3][2] += a.w * b.z; acc[3][3] += a.w * b.w;
        }
        __syncthreads();
    }

    float4 bv = make_float4(0.f, 0.f, 0.f, 0.f);
    if (!DUAL) bv = *(const float4*)&bias[tx << 2];

    #pragma unroll
    for (int i = 0; i < 4; i++) {
        int row = row0 + (ty << 2) + i;
        if (row >= M) continue;
        float4 v = make_float4(acc[i][0], acc[i][1], acc[i][2], acc[i][3]);
        if (DUAL) {
            *(float4*)&C[row * 64 + (tx << 2)] = v;
            float di = g_dinv[row];
            float w  = di * di;
            float4 v2 = make_float4(v.x * w, v.y * w, v.z * w, v.w * w);
            *(float4*)&C2[row * 64 + (tx << 2)] = v2;
        } else {
            v.x += bv.x; v.y += bv.y; v.z += bv.z; v.w += bv.w;
            if (RELU) {
                v.x = fmaxf(v.x, 0.f); v.y = fmaxf(v.y, 0.f);
                v.z = fmaxf(v.z, 0.f); v.w = fmaxf(v.w, 0.f);
            }
            *(float4*)&C[row * 64 + (tx << 2)] = v;
        }
    }
}

// ---------------- edge scatter: out[dst] += h[src] * dinv[src]*dinv[dst] ----------------
__device__ __forceinline__ void red_add_v4(float* addr, float4 v) {
    asm volatile("red.global.add.v4.f32 [%0], {%1, %2, %3, %4};"
                 :: "l"(addr), "f"(v.x), "f"(v.y), "f"(v.z), "f"(v.w) : "memory");
}

__global__ void scatter_kernel(const float* __restrict__ h, float* __restrict__ out,
                               const int* __restrict__ src, const int* __restrict__ dst) {
    int idx = blockIdx.x * 256 + threadIdx.x;   // 16 threads per edge
    int e = idx >> 4;
    if (e >= N_EDGES) return;
    int c4 = (idx & 15) << 2;
    int s = __ldg(&src[e]);
    int d = __ldg(&dst[e]);
    float w = g_dinv[s] * g_dinv[d];
    float4 v = *(const float4*)&h[s * 64 + c4];
    v.x *= w; v.y *= w; v.z *= w; v.w *= w;
    red_add_v4(&out[d * 64 + c4], v);
}

// ---------------- z = relu(z + bias), layer-1 post-aggregation ----------------
__global__ void bias_relu_kernel(float* __restrict__ z, const float* __restrict__ bias) {
    int idx = blockIdx.x * 256 + threadIdx.x;
    if (idx >= N_NODES * 16) return;
    int c4 = (idx & 15) << 2;
    float4 v = *(float4*)&z[idx << 2];
    float4 b = *(const float4*)&bias[c4];
    v.x = fmaxf(v.x + b.x, 0.f);
    v.y = fmaxf(v.y + b.y, 0.f);
    v.z = fmaxf(v.z + b.z, 0.f);
    v.w = fmaxf(v.w + b.w, 0.f);
    *(float4*)&z[idx << 2] = v;
}

// ---------------- decode gather: ef = (z2[a]+b2) * (z2[b]+b2) ----------------
__global__ void ef_kernel(const int* __restrict__ eli, const float* __restrict__ b2) {
    int idx = blockIdx.x * 256 + threadIdx.x;
    if (idx >= N_EL * 16) return;
    int p = idx >> 4, c4 = (idx & 15) << 2;
    int a = __ldg(&eli[p]);
    int b = __ldg(&eli[N_EL + p]);
    float4 bb = *(const float4*)&b2[c4];
    float4 za = *(const float4*)&g_z2[a * 64 + c4];
    float4 zb = *(const float4*)&g_z2[b * 64 + c4];
    float4 r;
    r.x = (za.x + bb.x) * (zb.x + bb.x);
    r.y = (za.y + bb.y) * (zb.y + bb.y);
    r.z = (za.z + bb.z) * (zb.z + bb.z);
    r.w = (za.w + bb.w) * (zb.w + bb.w);
    *(float4*)&g_ef[idx << 2] = r;
}

// ---------------- final: out[p] = dot(m2[p,:], P3) + pb3 ----------------
__global__ void final_kernel(const float* __restrict__ P3, const float* __restrict__ pb3,
                             float* __restrict__ out) {
    int gid  = blockIdx.x * 256 + threadIdx.x;
    int w    = gid >> 5;            // one warp per pair; grid sized exactly
    int lane = gid & 31;
    float s = g_m2[w * 64 + lane]      * __ldg(&P3[lane])
            + g_m2[w * 64 + 32 + lane] * __ldg(&P3[32 + lane]);
    #pragma unroll
    for (int o = 16; o > 0; o >>= 1) s += __shfl_down_sync(0xffffffffu, s, o);
    if (lane == 0) out[w] = s + __ldg(&pb3[0]);
}

// ---------------- launcher ----------------
extern "C" void kernel_launch(void* const* d_in, const int* in_sizes, int n_in,
                              void* d_out, int out_size)
{
    const float* x   = (const float*)d_in[0];
    const int*   ei  = (const int*)  d_in[1];
    const int*   eli = (const int*)  d_in[2];
    const float* W1  = (const float*)d_in[3];
    const float* b1  = (const float*)d_in[4];
    const float* W2  = (const float*)d_in[5];
    const float* b2  = (const float*)d_in[6];
    const float* P1  = (const float*)d_in[7];
    const float* pb1 = (const float*)d_in[8];
    const float* P2  = (const float*)d_in[9];
    const float* pb2 = (const float*)d_in[10];
    const float* P3  = (const float*)d_in[11];
    const float* pb3 = (const float*)d_in[12];
    float* out = (float*)d_out;

    const int* src = ei;
    const int* dst = ei + N_EDGES;

    float *ph1, *pz1, *ph2, *pz2, *pef, *pm1, *pm2;
    cudaGetSymbolAddress((void**)&ph1, g_h1);
    cudaGetSymbolAddress((void**)&pz1, g_z1);
    cudaGetSymbolAddress((void**)&ph2, g_h2);
    cudaGetSymbolAddress((void**)&pz2, g_z2);
    cudaGetSymbolAddress((void**)&pef, g_ef);
    cudaGetSymbolAddress((void**)&pm1, g_m1);
    cudaGetSymbolAddress((void**)&pm2, g_m2);

    // normalization coefficients
    zero_deg_kernel <<<(N_NODES + 255) / 256, 256>>>();
    count_deg_kernel<<<(N_EDGES + 255) / 256, 256>>>(dst);
    dinv_kernel     <<<(N_NODES + 255) / 256, 256>>>();

    const int gbN  = (N_NODES + 63) / 64;   // 782
    const int gbEL = (N_EL    + 63) / 64;   // 1563

    // conv layer 1: h1 = x@W1 ; z1 = self-loop term ; scatter ; bias+relu
    gemm64_kernel<128, true, false><<<gbN, 256>>>(x, W1, nullptr, ph1, pz1, N_NODES);
    scatter_kernel<<<(N_EDGES * 16) / 256, 256>>>(ph1, pz1, src, dst);
    bias_relu_kernel<<<(N_NODES * 16) / 256, 256>>>(pz1, b1);

    // conv layer 2: h2 = z1@W2 ; z2 = self-loop term ; scatter (b2 folded into ef)
    gemm64_kernel<64, true, false><<<gbN, 256>>>(pz1, W2, nullptr, ph2, pz2, N_NODES);
    scatter_kernel<<<(N_EDGES * 16) / 256, 256>>>(ph2, pz2, src, dst);

    // decode
    ef_kernel<<<(N_EL * 16) / 256, 256>>>(eli, b2);
    gemm64_kernel<64, false, true><<<gbEL, 256>>>(pef, P1, pb1, pm1, nullptr, N_EL);
    gemm64_kernel<64, false, true><<<gbEL, 256>>>(pm1, P2, pb2, pm2, nullptr, N_EL);
    final_kernel<<<(N_EL * 32) / 256, 256>>>(P3, pb3, out);
}

// round 3
// speedup vs baseline: 1.1376x; 1.1376x over previous
#include <cuda_runtime.h>
#include <cuda_bf16.h>
#include <cstdint>

#define N_NODES 50000
#define N_EDGES 800000
#define N_EL    100000

// ---------------- scratch (device globals; no allocation allowed) ----------------
__device__ float g_deg [N_NODES];
__device__ float g_dinv[N_NODES];
__device__ float g_h1  [N_NODES * 64];
__device__ float g_z1  [N_NODES * 64];
__device__ float g_h2  [N_NODES * 64];
__device__ float g_z2  [N_NODES * 64];
__device__ float g_ef  [N_EL * 64];
__device__ float g_m1  [N_EL * 64];
__device__ float g_m2  [N_EL * 64];

// ---------------- helpers ----------------
__device__ __forceinline__ uint32_t smem_u32(const void* p) {
    uint32_t a;
    asm("{ .reg .u64 t; cvta.to.shared.u64 t, %1; cvt.u32.u64 %0, t; }" : "=r"(a) : "l"(p));
    return a;
}
__device__ __forceinline__ uint32_t pack_bf16(float x, float y) {
    __nv_bfloat162 t = __floats2bfloat162_rn(x, y);
    return *(uint32_t*)&t;
}
__device__ __forceinline__ float bf_hi(float x) {
    return __bfloat162float(__float2bfloat16_rn(x));
}

__device__ __forceinline__ void ldsm_x4(uint32_t* r, uint32_t addr) {
    asm volatile("ldmatrix.sync.aligned.m8n8.x4.shared.b16 {%0,%1,%2,%3}, [%4];"
                 : "=r"(r[0]), "=r"(r[1]), "=r"(r[2]), "=r"(r[3]) : "r"(addr));
}
__device__ __forceinline__ void ldsm_x4_t(uint32_t* r, uint32_t addr) {
    asm volatile("ldmatrix.sync.aligned.m8n8.x4.trans.shared.b16 {%0,%1,%2,%3}, [%4];"
                 : "=r"(r[0]), "=r"(r[1]), "=r"(r[2]), "=r"(r[3]) : "r"(addr));
}
__device__ __forceinline__ void mma_bf16(float* d, const uint32_t* a, const uint32_t* b) {
    asm volatile("mma.sync.aligned.m16n8k16.row.col.f32.bf16.bf16.f32 "
                 "{%0,%1,%2,%3}, {%4,%5,%6,%7}, {%8,%9}, {%0,%1,%2,%3};"
                 : "+f"(d[0]), "+f"(d[1]), "+f"(d[2]), "+f"(d[3])
                 : "r"(a[0]), "r"(a[1]), "r"(a[2]), "r"(a[3]), "r"(b[0]), "r"(b[1]));
}

// ---------------- degree / normalization ----------------
__global__ void zero_deg_kernel() {
    int i = blockIdx.x * 256 + threadIdx.x;
    if (i < N_NODES) g_deg[i] = 0.0f;
}
__global__ void count_deg_kernel(const int* __restrict__ dst) {
    int e = blockIdx.x * 256 + threadIdx.x;
    if (e < N_EDGES) atomicAdd(&g_deg[dst[e]], 1.0f);
}
__global__ void dinv_kernel() {
    int i = blockIdx.x * 256 + threadIdx.x;
    if (i < N_NODES) g_dinv[i] = rsqrtf(g_deg[i] + 1.0f);  // +1 = self-loop
}

// ---------------- mma.sync bf16x3 GEMM: C[M,64] = A[M,K] @ B[K,64] ----------------
// D = Ah*Bh + Ah*Bl + Al*Bh  (fp32 accum; dropped Al*Bl <= 2^-18 rel)
// DUAL:  C = product, C2 = product * dinv[row]^2
// !DUAL: C = relu?(product + bias)
template<int K, bool DUAL, bool RELU>
__global__ __launch_bounds__(256)
void mma_gemm(const float* __restrict__ A, const float* __restrict__ B,
              const float* __restrict__ bias, float* __restrict__ C,
              float* __restrict__ C2, int M)
{
    constexpr int SA_H = K + 8;                 // halves per A row (16B pad)
    constexpr int SB_H = 72;                    // halves per B row (64 + 8)
    constexpr int A_HI = 0;
    constexpr int A_LO = 128 * SA_H * 2;
    constexpr int B_HI = 2 * 128 * SA_H * 2;
    constexpr int B_LO = B_HI + K * SB_H * 2;

    extern __shared__ char smem[];
    const uint32_t sbase = smem_u32(smem);
    const int tid  = threadIdx.x;
    const int wid  = tid >> 5;
    const int lane = tid & 31;
    const int row0 = blockIdx.x * 128;

    // ---- stage A hi/lo (coalesced float4 reads) ----
    constexpr int KV4 = K / 4;
    for (int idx = tid; idx < 128 * KV4; idx += 256) {
        int r  = idx / KV4;
        int kc = (idx - r * KV4) * 4;
        float4 v = make_float4(0.f, 0.f, 0.f, 0.f);
        int row = row0 + r;
        if (row < M) v = *(const float4*)&A[(size_t)row * K + kc];
        float hx = bf_hi(v.x), hy = bf_hi(v.y), hz = bf_hi(v.z), hw = bf_hi(v.w);
        uint32_t off = (uint32_t)(r * SA_H + kc) * 2;
        *(uint2*)(smem + A_HI + off) = make_uint2(pack_bf16(hx, hy), pack_bf16(hz, hw));
        *(uint2*)(smem + A_LO + off) = make_uint2(pack_bf16(v.x - hx, v.y - hy),
                                                  pack_bf16(v.z - hz, v.w - hw));
    }
    // ---- stage B hi/lo, [k][n] row-major ----
    for (int idx = tid; idx < K * 16; idx += 256) {
        int k = idx >> 4, nc = (idx & 15) * 4;
        float4 v = *(const float4*)&B[k * 64 + nc];
        float hx = bf_hi(v.x), hy = bf_hi(v.y), hz = bf_hi(v.z), hw = bf_hi(v.w);
        uint32_t off = (uint32_t)(k * SB_H + nc) * 2;
        *(uint2*)(smem + B_HI + off) = make_uint2(pack_bf16(hx, hy), pack_bf16(hz, hw));
        *(uint2*)(smem + B_LO + off) = make_uint2(pack_bf16(v.x - hx, v.y - hy),
                                                  pack_bf16(v.z - hz, v.w - hw));
    }
    __syncthreads();

    // ---- warp tiles: 4 (M) x 2 (N); each warp 32 rows x 32 cols ----
    const int wm = (wid & 3) * 32;
    const int wn = (wid >> 2) * 32;
    const int lrow = lane & 15;            // ldmatrix row within 16
    const int lsel = (lane >> 4) * 8;      // column-half selector

    float acc[2][4][4];
    #pragma unroll
    for (int mt = 0; mt < 2; mt++)
        #pragma unroll
        for (int nt = 0; nt < 4; nt++)
            #pragma unroll
            for (int i = 0; i < 4; i++) acc[mt][nt][i] = 0.f;

    #pragma unroll
    for (int k0 = 0; k0 < K; k0 += 16) {
        uint32_t a_hi[2][4], a_lo[2][4];
        #pragma unroll
        for (int mt = 0; mt < 2; mt++) {
            uint32_t off = (uint32_t)((wm + 16 * mt + lrow) * SA_H + k0 + lsel) * 2;
            ldsm_x4(a_hi[mt], sbase + A_HI + off);
            ldsm_x4(a_lo[mt], sbase + A_LO + off);
        }
        uint32_t b_hi[2][4], b_lo[2][4];   // [n-half][b0/b1 of even nt, b0/b1 of odd nt]
        #pragma unroll
        for (int h = 0; h < 2; h++) {
            uint32_t off = (uint32_t)((k0 + lrow) * SB_H + wn + 16 * h + lsel) * 2;
            ldsm_x4_t(b_hi[h], sbase + B_HI + off);
            ldsm_x4_t(b_lo[h], sbase + B_LO + off);
        }
        #pragma unroll
        for (int mt = 0; mt < 2; mt++)
            #pragma unroll
            for (int nt = 0; nt < 4; nt++) {
                const uint32_t* bh = &b_hi[nt >> 1][(nt & 1) * 2];
                const uint32_t* bl = &b_lo[nt >> 1][(nt & 1) * 2];
                mma_bf16(acc[mt][nt], a_hi[mt], bh);
                mma_bf16(acc[mt][nt], a_hi[mt], bl);
                mma_bf16(acc[mt][nt], a_lo[mt], bh);
            }
    }

    // ---- epilogue: direct global stores (float2 per fragment half) ----
    const int g  = lane >> 2;
    const int tg = lane & 3;
    #pragma unroll
    for (int mt = 0; mt < 2; mt++) {
        #pragma unroll
        for (int rh = 0; rh < 2; rh++) {
            int row = row0 + wm + 16 * mt + g + 8 * rh;
            if (row >= M) continue;
            float w = 0.f;
            if (DUAL) { float di = g_dinv[row]; w = di * di; }
            #pragma unroll
            for (int nt = 0; nt < 4; nt++) {
                int col = wn + 8 * nt + 2 * tg;
                float vx = acc[mt][nt][2 * rh];
                float vy = acc[mt][nt][2 * rh + 1];
                if (DUAL) {
                    *(float2*)&C [(size_t)row * 64 + col] = make_float2(vx, vy);
                    *(float2*)&C2[(size_t)row * 64 + col] = make_float2(vx * w, vy * w);
                } else {
                    vx += bias[col]; vy += bias[col + 1];
                    if (RELU) { vx = fmaxf(vx, 0.f); vy = fmaxf(vy, 0.f); }
                    *(float2*)&C[(size_t)row * 64 + col] = make_float2(vx, vy);
                }
            }
        }
    }
}

// ---------------- edge scatter: out[dst] += h[src] * dinv[src]*dinv[dst] ----------------
__device__ __forceinline__ void red_add_v4(float* addr, float4 v) {
    asm volatile("red.global.add.v4.f32 [%0], {%1, %2, %3, %4};"
                 :: "l"(addr), "f"(v.x), "f"(v.y), "f"(v.z), "f"(v.w) : "memory");
}

__global__ void scatter_kernel(const float* __restrict__ h, float* __restrict__ out,
                               const int* __restrict__ src, const int* __restrict__ dst) {
    int idx = blockIdx.x * 256 + threadIdx.x;   // 16 threads per edge
    int e = idx >> 4;
    if (e >= N_EDGES) return;
    int c4 = (idx & 15) << 2;
    int s = __ldg(&src[e]);
    int d = __ldg(&dst[e]);
    float w = g_dinv[s] * g_dinv[d];
    float4 v = *(const float4*)&h[s * 64 + c4];
    v.x *= w; v.y *= w; v.z *= w; v.w *= w;
    red_add_v4(&out[d * 64 + c4], v);
}

// ---------------- z = relu(z + bias) ----------------
__global__ void bias_relu_kernel(float* __restrict__ z, const float* __restrict__ bias) {
    int idx = blockIdx.x * 256 + threadIdx.x;
    if (idx >= N_NODES * 16) return;
    int c4 = (idx & 15) << 2;
    float4 v = *(float4*)&z[idx << 2];
    float4 b = *(const float4*)&bias[c4];
    v.x = fmaxf(v.x + b.x, 0.f);
    v.y = fmaxf(v.y + b.y, 0.f);
    v.z = fmaxf(v.z + b.z, 0.f);
    v.w = fmaxf(v.w + b.w, 0.f);
    *(float4*)&z[idx << 2] = v;
}

// ---------------- decode gather: ef = (z2[a]+b2) * (z2[b]+b2) ----------------
__global__ void ef_kernel(const int* __restrict__ eli, const float* __restrict__ b2) {
    int idx = blockIdx.x * 256 + threadIdx.x;
    if (idx >= N_EL * 16) return;
    int p = idx >> 4, c4 = (idx & 15) << 2;
    int a = __ldg(&eli[p]);
    int b = __ldg(&eli[N_EL + p]);
    float4 bb = *(const float4*)&b2[c4];
    float4 za = *(const float4*)&g_z2[a * 64 + c4];
    float4 zb = *(const float4*)&g_z2[b * 64 + c4];
    float4 r;
    r.x = (za.x + bb.x) * (zb.x + bb.x);
    r.y = (za.y + bb.y) * (zb.y + bb.y);
    r.z = (za.z + bb.z) * (zb.z + bb.z);
    r.w = (za.w + bb.w) * (zb.w + bb.w);
    *(float4*)&g_ef[idx << 2] = r;
}

// ---------------- final: out[p] = dot(m2[p,:], P3) + pb3 ----------------
__global__ void final_kernel(const float* __restrict__ P3, const float* __restrict__ pb3,
                             float* __restrict__ out) {
    int gid  = blockIdx.x * 256 + threadIdx.x;
    int w    = gid >> 5;
    int lane = gid & 31;
    float s = g_m2[w * 64 + lane]      * __ldg(&P3[lane])
            + g_m2[w * 64 + 32 + lane] * __ldg(&P3[32 + lane]);
    #pragma unroll
    for (int o = 16; o > 0; o >>= 1) s += __shfl_down_sync(0xffffffffu, s, o);
    if (lane == 0) out[w] = s + __ldg(&pb3[0]);
}

// ---------------- launcher ----------------
extern "C" void kernel_launch(void* const* d_in, const int* in_sizes, int n_in,
                              void* d_out, int out_size)
{
    const float* x   = (const float*)d_in[0];
    const int*   ei  = (const int*)  d_in[1];
    const int*   eli = (const int*)  d_in[2];
    const float* W1  = (const float*)d_in[3];
    const float* b1  = (const float*)d_in[4];
    const float* W2  = (const float*)d_in[5];
    const float* b2  = (const float*)d_in[6];
    const float* P1  = (const float*)d_in[7];
    const float* pb1 = (const float*)d_in[8];
    const float* P2  = (const float*)d_in[9];
    const float* pb2 = (const float*)d_in[10];
    const float* P3  = (const float*)d_in[11];
    const float* pb3 = (const float*)d_in[12];
    float* out = (float*)d_out;

    const int* src = ei;
    const int* dst = ei + N_EDGES;

    float *ph1, *pz1, *ph2, *pz2, *pef, *pm1, *pm2;
    cudaGetSymbolAddress((void**)&ph1, g_h1);
    cudaGetSymbolAddress((void**)&pz1, g_z1);
    cudaGetSymbolAddress((void**)&ph2, g_h2);
    cudaGetSymbolAddress((void**)&pz2, g_z2);
    cudaGetSymbolAddress((void**)&pef, g_ef);
    cudaGetSymbolAddress((void**)&pm1, g_m1);
    cudaGetSymbolAddress((void**)&pm2, g_m2);

    // dynamic smem: A hi/lo + B hi/lo
    const int SM128 = 2 * 128 * (128 + 8) * 2 + 2 * 128 * 72 * 2;  // 106496
    const int SM64  = 2 * 128 * (64 + 8) * 2  + 2 * 64 * 72 * 2;   //  55296
    cudaFuncSetAttribute(mma_gemm<128, true,  false>, cudaFuncAttributeMaxDynamicSharedMemorySize, SM128);
    cudaFuncSetAttribute(mma_gemm<64,  true,  false>, cudaFuncAttributeMaxDynamicSharedMemorySize, SM64);
    cudaFuncSetAttribute(mma_gemm<64,  false, true >, cudaFuncAttributeMaxDynamicSharedMemorySize, SM64);

    // normalization coefficients
    zero_deg_kernel <<<(N_NODES + 255) / 256, 256>>>();
    count_deg_kernel<<<(N_EDGES + 255) / 256, 256>>>(dst);
    dinv_kernel     <<<(N_NODES + 255) / 256, 256>>>();

    const int gbN  = (N_NODES + 127) / 128;   // 391
    const int gbEL = (N_EL    + 127) / 128;   // 782

    // conv layer 1
    mma_gemm<128, true, false><<<gbN, 256, SM128>>>(x, W1, nullptr, ph1, pz1, N_NODES);
    scatter_kernel<<<(N_EDGES * 16) / 256, 256>>>(ph1, pz1, src, dst);
    bias_relu_kernel<<<(N_NODES * 16) / 256, 256>>>(pz1, b1);

    // conv layer 2 (b2 folded into ef)
    mma_gemm<64, true, false><<<gbN, 256, SM64>>>(pz1, W2, nullptr, ph2, pz2, N_NODES);
    scatter_kernel<<<(N_EDGES * 16) / 256, 256>>>(ph2, pz2, src, dst);

    // decode
    ef_kernel<<<(N_EL * 16) / 256, 256>>>(eli, b2);
    mma_gemm<64, false, true><<<gbEL, 256, SM64>>>(pef, P1, pb1, pm1, nullptr, N_EL);
    mma_gemm<64, false, true><<<gbEL, 256, SM64>>>(pm1, P2, pb2, pm2, nullptr, N_EL);
    final_kernel<<<(N_EL * 32) / 256, 256>>>(P3, pb3, out);
}

// round 4
// speedup vs baseline: 1.3249x; 1.1646x over previous
#include <cuda_runtime.h>
#include <cuda_bf16.h>
#include <cstdint>

#define N_NODES 50000
#define N_EDGES 800000
#define N_EL    100000

// ---------------- scratch (device globals; no allocation allowed) ----------------
__device__ float g_deg [N_NODES];
__device__ float g_dinv[N_NODES];
__device__ float g_h1  [N_NODES * 64];
__device__ float g_z1  [N_NODES * 64];
__device__ float g_h2  [N_NODES * 64];
__device__ float g_z2  [N_NODES * 64];
// pre-split bf16 operand arrays
__device__ __nv_bfloat16 g_xhi [N_NODES * 128];
__device__ __nv_bfloat16 g_xlo [N_NODES * 128];
__device__ __nv_bfloat16 g_z1hi[N_NODES * 64];
__device__ __nv_bfloat16 g_z1lo[N_NODES * 64];
__device__ __nv_bfloat16 g_w1hi[128 * 64];
__device__ __nv_bfloat16 g_w1lo[128 * 64];
__device__ __nv_bfloat16 g_w2hi[64 * 64];
__device__ __nv_bfloat16 g_w2lo[64 * 64];

// ---------------- helpers ----------------
__device__ __forceinline__ uint32_t smem_u32(const void* p) {
    uint32_t a;
    asm("{ .reg .u64 t; cvta.to.shared.u64 t, %1; cvt.u32.u64 %0, t; }" : "=r"(a) : "l"(p));
    return a;
}
__device__ __forceinline__ uint32_t pack_bf16(float x, float y) {
    __nv_bfloat162 t = __floats2bfloat162_rn(x, y);
    return *(uint32_t*)&t;
}
__device__ __forceinline__ float bf_hi(float x) {
    return __bfloat162float(__float2bfloat16_rn(x));
}
__device__ __forceinline__ void cp16(uint32_t dst, const void* src, uint32_t sz) {
    asm volatile("cp.async.ca.shared.global [%0], [%1], 16, %2;"
                 :: "r"(dst), "l"(src), "r"(sz) : "memory");
}
__device__ __forceinline__ void cp_commit_wait() {
    asm volatile("cp.async.commit_group;");
    asm volatile("cp.async.wait_group 0;" ::: "memory");
}
__device__ __forceinline__ void ldsm_x4(uint32_t* r, uint32_t addr) {
    asm volatile("ldmatrix.sync.aligned.m8n8.x4.shared.b16 {%0,%1,%2,%3}, [%4];"
                 : "=r"(r[0]), "=r"(r[1]), "=r"(r[2]), "=r"(r[3]) : "r"(addr));
}
__device__ __forceinline__ void ldsm_x4_t(uint32_t* r, uint32_t addr) {
    asm volatile("ldmatrix.sync.aligned.m8n8.x4.trans.shared.b16 {%0,%1,%2,%3}, [%4];"
                 : "=r"(r[0]), "=r"(r[1]), "=r"(r[2]), "=r"(r[3]) : "r"(addr));
}
__device__ __forceinline__ void mma_bf16(float* d, const uint32_t* a, const uint32_t* b) {
    asm volatile("mma.sync.aligned.m16n8k16.row.col.f32.bf16.bf16.f32 "
                 "{%0,%1,%2,%3}, {%4,%5,%6,%7}, {%8,%9}, {%0,%1,%2,%3};"
                 : "+f"(d[0]), "+f"(d[1]), "+f"(d[2]), "+f"(d[3])
                 : "r"(a[0]), "r"(a[1]), "r"(a[2]), "r"(a[3]), "r"(b[0]), "r"(b[1]));
}

// ---------------- degree / normalization ----------------
__global__ void zero_deg_kernel() {
    int i = blockIdx.x * 256 + threadIdx.x;
    if (i < N_NODES) g_deg[i] = 0.0f;
}
__global__ void count_deg_kernel(const int* __restrict__ dst) {
    int e = blockIdx.x * 256 + threadIdx.x;
    if (e < N_EDGES) atomicAdd(&g_deg[dst[e]], 1.0f);
}
__global__ void dinv_kernel() {
    int i = blockIdx.x * 256 + threadIdx.x;
    if (i < N_NODES) g_dinv[i] = rsqrtf(g_deg[i] + 1.0f);  // +1 = self-loop
}

// ---------------- generic fp32 -> bf16 hi/lo split (float4 granular) ----------------
__global__ void split_kernel(const float* __restrict__ in,
                             __nv_bfloat16* __restrict__ hi,
                             __nv_bfloat16* __restrict__ lo, int n4) {
    int i = blockIdx.x * 256 + threadIdx.x;
    if (i >= n4) return;
    float4 v = ((const float4*)in)[i];
    float hx = bf_hi(v.x), hy = bf_hi(v.y), hz = bf_hi(v.z), hw = bf_hi(v.w);
    ((uint2*)hi)[i] = make_uint2(pack_bf16(hx, hy), pack_bf16(hz, hw));
    ((uint2*)lo)[i] = make_uint2(pack_bf16(v.x - hx, v.y - hy), pack_bf16(v.z - hz, v.w - hw));
}

// ---------------- pre-split mma GEMM: C[M,64] = A[M,K] @ B[K,64] ----------------
// A,B given as bf16 hi/lo arrays. D = Ah*Bh + Ah*Bl + Al*Bh (fp32 accum).
// C = product, C2 = product * dinv[row]^2
template<int K>
__global__ __launch_bounds__(256)
void mma_gemm_pre(const __nv_bfloat16* __restrict__ Ahi, const __nv_bfloat16* __restrict__ Alo,
                  const __nv_bfloat16* __restrict__ Bhi, const __nv_bfloat16* __restrict__ Blo,
                  float* __restrict__ C, float* __restrict__ C2, int M)
{
    constexpr int SA_H = K + 8;
    constexpr int SB_H = 72;
    constexpr int A_HI = 0;
    constexpr int A_LO = 128 * SA_H * 2;
    constexpr int B_HI = 2 * 128 * SA_H * 2;
    constexpr int B_LO = B_HI + K * SB_H * 2;

    extern __shared__ char smem[];
    const uint32_t sbase = smem_u32(smem);
    const int tid  = threadIdx.x;
    const int wid  = tid >> 5;
    const int lane = tid & 31;
    const int row0 = blockIdx.x * 128;

    // ---- stage A hi/lo via cp.async (8 halves = 16B per chunk) ----
    constexpr int ACH = K / 8;
    #pragma unroll
    for (int idx = tid; idx < 128 * ACH; idx += 256) {
        int r  = idx / ACH;
        int kc = (idx - r * ACH) * 8;
        int row = row0 + r;
        uint32_t sz = (row < M) ? 16u : 0u;
        size_t goff = (size_t)(row < M ? row : 0) * K + kc;
        uint32_t d = sbase + A_HI + (uint32_t)(r * SA_H + kc) * 2;
        cp16(d,                 &Ahi[goff], sz);
        cp16(d + (A_LO - A_HI), &Alo[goff], sz);
    }
    // ---- stage B hi/lo ----
    #pragma unroll
    for (int idx = tid; idx < K * 8; idx += 256) {
        int k = idx >> 3, nc = (idx & 7) * 8;
        uint32_t d = sbase + B_HI + (uint32_t)(k * SB_H + nc) * 2;
        cp16(d,                 &Bhi[k * 64 + nc], 16u);
        cp16(d + (B_LO - B_HI), &Blo[k * 64 + nc], 16u);
    }
    cp_commit_wait();
    __syncthreads();

    // ---- warp tiles: 4 (M) x 2 (N); each warp 32 rows x 32 cols ----
    const int wm = (wid & 3) * 32;
    const int wn = (wid >> 2) * 32;
    const int lrow = lane & 15;
    const int lsel = (lane >> 4) * 8;

    float acc[2][4][4];
    #pragma unroll
    for (int mt = 0; mt < 2; mt++)
        #pragma unroll
        for (int nt = 0; nt < 4; nt++)
            #pragma unroll
            for (int i = 0; i < 4; i++) acc[mt][nt][i] = 0.f;

    #pragma unroll
    for (int k0 = 0; k0 < K; k0 += 16) {
        uint32_t a_hi[2][4], a_lo[2][4];
        #pragma unroll
        for (int mt = 0; mt < 2; mt++) {
            uint32_t off = (uint32_t)((wm + 16 * mt + lrow) * SA_H + k0 + lsel) * 2;
            ldsm_x4(a_hi[mt], sbase + A_HI + off);
            ldsm_x4(a_lo[mt], sbase + A_LO + off);
        }
        uint32_t b_hi[2][4], b_lo[2][4];
        #pragma unroll
        for (int h = 0; h < 2; h++) {
            uint32_t off = (uint32_t)((k0 + lrow) * SB_H + wn + 16 * h + lsel) * 2;
            ldsm_x4_t(b_hi[h], sbase + B_HI + off);
            ldsm_x4_t(b_lo[h], sbase + B_LO + off);
        }
        #pragma unroll
        for (int mt = 0; mt < 2; mt++)
            #pragma unroll
            for (int nt = 0; nt < 4; nt++) {
                const uint32_t* bh = &b_hi[nt >> 1][(nt & 1) * 2];
                const uint32_t* bl = &b_lo[nt >> 1][(nt & 1) * 2];
                mma_bf16(acc[mt][nt], a_hi[mt], bh);
                mma_bf16(acc[mt][nt], a_hi[mt], bl);
                mma_bf16(acc[mt][nt], a_lo[mt], bh);
            }
    }

    // ---- epilogue: C = prod, C2 = prod * dinv^2 ----
    const int g  = lane >> 2;
    const int tg = lane & 3;
    #pragma unroll
    for (int mt = 0; mt < 2; mt++) {
        #pragma unroll
        for (int rh = 0; rh < 2; rh++) {
            int row = row0 + wm + 16 * mt + g + 8 * rh;
            if (row >= M) continue;
            float di = g_dinv[row];
            float w  = di * di;
            #pragma unroll
            for (int nt = 0; nt < 4; nt++) {
                int col = wn + 8 * nt + 2 * tg;
                float vx = acc[mt][nt][2 * rh];
                float vy = acc[mt][nt][2 * rh + 1];
                *(float2*)&C [(size_t)row * 64 + col] = make_float2(vx, vy);
                *(float2*)&C2[(size_t)row * 64 + col] = make_float2(vx * w, vy * w);
            }
        }
    }
}

// ---------------- edge scatter: out[dst] += h[src] * dinv[src]*dinv[dst] ----------------
__device__ __forceinline__ void red_add_v4(float* addr, float4 v) {
    asm volatile("red.global.add.v4.f32 [%0], {%1, %2, %3, %4};"
                 :: "l"(addr), "f"(v.x), "f"(v.y), "f"(v.z), "f"(v.w) : "memory");
}

__global__ void scatter_kernel(const float* __restrict__ h, float* __restrict__ out,
                               const int* __restrict__ src, const int* __restrict__ dst) {
    int idx = blockIdx.x * 256 + threadIdx.x;   // 16 threads per edge
    int e = idx >> 4;
    if (e >= N_EDGES) return;
    int c4 = (idx & 15) << 2;
    int s = __ldg(&src[e]);
    int d = __ldg(&dst[e]);
    float w = g_dinv[s] * g_dinv[d];
    float4 v = *(const float4*)&h[s * 64 + c4];
    v.x *= w; v.y *= w; v.z *= w; v.w *= w;
    red_add_v4(&out[d * 64 + c4], v);
}

// ---------------- z1 = relu(z1 + b1); also emit bf16 hi/lo splits ----------------
__global__ void bias_relu_split_kernel(float* __restrict__ z, const float* __restrict__ bias) {
    int idx = blockIdx.x * 256 + threadIdx.x;
    if (idx >= N_NODES * 16) return;
    int c4 = (idx & 15) << 2;
    float4 v = *(float4*)&z[idx << 2];
    float4 b = *(const float4*)&bias[c4];
    v.x = fmaxf(v.x + b.x, 0.f);
    v.y = fmaxf(v.y + b.y, 0.f);
    v.z = fmaxf(v.z + b.z, 0.f);
    v.w = fmaxf(v.w + b.w, 0.f);
    *(float4*)&z[idx << 2] = v;
    float hx = bf_hi(v.x), hy = bf_hi(v.y), hz = bf_hi(v.z), hw = bf_hi(v.w);
    ((uint2*)g_z1hi)[idx] = make_uint2(pack_bf16(hx, hy), pack_bf16(hz, hw));
    ((uint2*)g_z1lo)[idx] = make_uint2(pack_bf16(v.x - hx, v.y - hy), pack_bf16(v.z - hz, v.w - hw));
}

// ---------------- fused decode: ef -> P1+relu -> P2+relu -> P3 dot ----------------
__global__ __launch_bounds__(256)
void decode_kernel(const int* __restrict__ eli, const float* __restrict__ b2,
                   const float* __restrict__ P1, const float* __restrict__ pb1,
                   const float* __restrict__ P2, const float* __restrict__ pb2,
                   const float* __restrict__ P3, const float* __restrict__ pb3,
                   float* __restrict__ out)
{
    constexpr int SA_H = 72, SB_H = 72;
    constexpr int EF_HI = 0;
    constexpr int EF_LO = 128 * SA_H * 2;            // 18432
    constexpr int P1_HI = 2 * 128 * SA_H * 2;        // 36864
    constexpr int P1_LO = P1_HI + 64 * SB_H * 2;     // 46080
    constexpr int P2_HI = P1_LO + 64 * SB_H * 2;     // 55296
    constexpr int P2_LO = P2_HI + 64 * SB_H * 2;     // 64512
    constexpr int S_OUT = P2_LO + 64 * SB_H * 2;     // 73728

    extern __shared__ char smem[];
    const uint32_t sbase = smem_u32(smem);
    const int tid  = threadIdx.x;
    const int wid  = tid >> 5;
    const int lane = tid & 31;
    const int row0 = blockIdx.x * 128;

    if (tid < 128) *(float*)(smem + S_OUT + tid * 4) = 0.f;

    // ---- stage ef = (z2[a]+b2)*(z2[b]+b2), split to bf16 hi/lo ----
    #pragma unroll
    for (int idx = tid; idx < 128 * 16; idx += 256) {
        int pl = idx >> 4, c4 = (idx & 15) << 2;
        int p = row0 + pl;
        float4 r = make_float4(0.f, 0.f, 0.f, 0.f);
        if (p < N_EL) {
            int a = __ldg(&eli[p]);
            int b = __ldg(&eli[N_EL + p]);
            float4 bb = *(const float4*)&b2[c4];
            float4 za = *(const float4*)&g_z2[a * 64 + c4];
            float4 zb = *(const float4*)&g_z2[b * 64 + c4];
            r.x = (za.x + bb.x) * (zb.x + bb.x);
            r.y = (za.y + bb.y) * (zb.y + bb.y);
            r.z = (za.z + bb.z) * (zb.z + bb.z);
            r.w = (za.w + bb.w) * (zb.w + bb.w);
        }
        float hx = bf_hi(r.x), hy = bf_hi(r.y), hz = bf_hi(r.z), hw = bf_hi(r.w);
        uint32_t off = (uint32_t)(pl * SA_H + c4) * 2;
        *(uint2*)(smem + EF_HI + off) = make_uint2(pack_bf16(hx, hy), pack_bf16(hz, hw));
        *(uint2*)(smem + EF_LO + off) = make_uint2(pack_bf16(r.x - hx, r.y - hy),
                                                   pack_bf16(r.z - hz, r.w - hw));
    }
    // ---- stage P1, P2 hi/lo ----
    #pragma unroll
    for (int idx = tid; idx < 64 * 16; idx += 256) {
        int k = idx >> 4, nc = (idx & 15) << 2;
        uint32_t off = (uint32_t)(k * SB_H + nc) * 2;
        float4 v = *(const float4*)&P1[k * 64 + nc];
        float hx = bf_hi(v.x), hy = bf_hi(v.y), hz = bf_hi(v.z), hw = bf_hi(v.w);
        *(uint2*)(smem + P1_HI + off) = make_uint2(pack_bf16(hx, hy), pack_bf16(hz, hw));
        *(uint2*)(smem + P1_LO + off) = make_uint2(pack_bf16(v.x - hx, v.y - hy),
                                                   pack_bf16(v.z - hz, v.w - hw));
        float4 u = *(const float4*)&P2[k * 64 + nc];
        float ux = bf_hi(u.x), uy = bf_hi(u.y), uz = bf_hi(u.z), uw = bf_hi(u.w);
        *(uint2*)(smem + P2_HI + off) = make_uint2(pack_bf16(ux, uy), pack_bf16(uz, uw));
        *(uint2*)(smem + P2_LO + off) = make_uint2(pack_bf16(u.x - ux, u.y - uy),
                                                   pack_bf16(u.z - uz, u.w - uw));
    }
    __syncthreads();

    const int wm = (wid & 3) * 32;
    const int wn = (wid >> 2) * 32;
    const int lrow = lane & 15;
    const int lsel = (lane >> 4) * 8;
    const int g  = lane >> 2;
    const int tg = lane & 3;

    // ---- mma1: h1 = ef @ P1 ----
    float acc[2][4][4];
    #pragma unroll
    for (int mt = 0; mt < 2; mt++)
        #pragma unroll
        for (int nt = 0; nt < 4; nt++)
            #pragma unroll
            for (int i = 0; i < 4; i++) acc[mt][nt][i] = 0.f;

    #pragma unroll
    for (int k0 = 0; k0 < 64; k0 += 16) {
        uint32_t a_hi[2][4], a_lo[2][4];
        #pragma unroll
        for (int mt = 0; mt < 2; mt++) {
            uint32_t off = (uint32_t)((wm + 16 * mt + lrow) * SA_H + k0 + lsel) * 2;
            ldsm_x4(a_hi[mt], sbase + EF_HI + off);
            ldsm_x4(a_lo[mt], sbase + EF_LO + off);
        }
        uint32_t b_hi[2][4], b_lo[2][4];
        #pragma unroll
        for (int h = 0; h < 2; h++) {
            uint32_t off = (uint32_t)((k0 + lrow) * SB_H + wn + 16 * h + lsel) * 2;
            ldsm_x4_t(b_hi[h], sbase + P1_HI + off);
            ldsm_x4_t(b_lo[h], sbase + P1_LO + off);
        }
        #pragma unroll
        for (int mt = 0; mt < 2; mt++)
            #pragma unroll
            for (int nt = 0; nt < 4; nt++) {
                const uint32_t* bh = &b_hi[nt >> 1][(nt & 1) * 2];
                const uint32_t* bl = &b_lo[nt >> 1][(nt & 1) * 2];
                mma_bf16(acc[mt][nt], a_hi[mt], bh);
                mma_bf16(acc[mt][nt], a_hi[mt], bl);
                mma_bf16(acc[mt][nt], a_lo[mt], bh);
            }
    }
    __syncthreads();   // all reads of EF region done

    // ---- h1 = relu(acc + pb1); write splits back into EF region ----
    #pragma unroll
    for (int mt = 0; mt < 2; mt++)
        #pragma unroll
        for (int rh = 0; rh < 2; rh++) {
            int rl = wm + 16 * mt + g + 8 * rh;
            #pragma unroll
            for (int nt = 0; nt < 4; nt++) {
                int col = wn + 8 * nt + 2 * tg;
                float vx = fmaxf(acc[mt][nt][2 * rh]     + __ldg(&pb1[col]),     0.f);
                float vy = fmaxf(acc[mt][nt][2 * rh + 1] + __ldg(&pb1[col + 1]), 0.f);
                float hx = bf_hi(vx), hy = bf_hi(vy);
                uint32_t off = (uint32_t)(rl * SA_H + col) * 2;
                *(uint32_t*)(smem + EF_HI + off) = pack_bf16(hx, hy);
                *(uint32_t*)(smem + EF_LO + off) = pack_bf16(vx - hx, vy - hy);
            }
        }
    __syncthreads();

    // ---- mma2: h2 = h1 @ P2 ----
    #pragma unroll
    for (int mt = 0; mt < 2; mt++)
        #pragma unroll
        for (int nt = 0; nt < 4; nt++)
            #pragma unroll
            for (int i = 0; i < 4; i++) acc[mt][nt][i] = 0.f;

    #pragma unroll
    for (int k0 = 0; k0 < 64; k0 += 16) {
        uint32_t a_hi[2][4], a_lo[2][4];
        #pragma unroll
        for (int mt = 0; mt < 2; mt++) {
            uint32_t off = (uint32_t)((wm + 16 * mt + lrow) * SA_H + k0 + lsel) * 2;
            ldsm_x4(a_hi[mt], sbase + EF_HI + off);
            ldsm_x4(a_lo[mt], sbase + EF_LO + off);
        }
        uint32_t b_hi[2][4], b_lo[2][4];
        #pragma unroll
        for (int h = 0; h < 2; h++) {
            uint32_t off = (uint32_t)((k0 + lrow) * SB_H + wn + 16 * h + lsel) * 2;
            ldsm_x4_t(b_hi[h], sbase + P2_HI + off);
            ldsm_x4_t(b_lo[h], sbase + P2_LO + off);
        }
        #pragma unroll
        for (int mt = 0; mt < 2; mt++)
            #pragma unroll
            for (int nt = 0; nt < 4; nt++) {
                const uint32_t* bh = &b_hi[nt >> 1][(nt & 1) * 2];
                const uint32_t* bl = &b_lo[nt >> 1][(nt & 1) * 2];
                mma_bf16(acc[mt][nt], a_hi[mt], bh);
                mma_bf16(acc[mt][nt], a_hi[mt], bl);
                mma_bf16(acc[mt][nt], a_lo[mt], bh);
            }
    }

    // ---- final: out[p] = dot(relu(h2 + pb2), P3) + pb3 ----
    #pragma unroll
    for (int mt = 0; mt < 2; mt++)
        #pragma unroll
        for (int rh = 0; rh < 2; rh++) {
            float s = 0.f;
            #pragma unroll
            for (int nt = 0; nt < 4; nt++) {
                int col = wn + 8 * nt + 2 * tg;
                float vx = fmaxf(acc[mt][nt][2 * rh]     + __ldg(&pb2[col]),     0.f);
                float vy = fmaxf(acc[mt][nt][2 * rh + 1] + __ldg(&pb2[col + 1]), 0.f);
                s += vx * __ldg(&P3[col]) + vy * __ldg(&P3[col + 1]);
            }
            s += __shfl_xor_sync(0xffffffffu, s, 1);
            s += __shfl_xor_sync(0xffffffffu, s, 2);
            if (tg == 0) {
                int rl = wm + 16 * mt + g + 8 * rh;
                atomicAdd((float*)(smem + S_OUT) + rl, s);
            }
        }
    __syncthreads();
    if (tid < 128) {
        int p = row0 + tid;
        if (p < N_EL) out[p] = *(float*)(smem + S_OUT + tid * 4) + __ldg(&pb3[0]);
    }
}

// ---------------- launcher ----------------
extern "C" void kernel_launch(void* const* d_in, const int* in_sizes, int n_in,
                              void* d_out, int out_size)
{
    const float* x   = (const float*)d_in[0];
    const int*   ei  = (const int*)  d_in[1];
    const int*   eli = (const int*)  d_in[2];
    const float* W1  = (const float*)d_in[3];
    const float* b1  = (const float*)d_in[4];
    const float* W2  = (const float*)d_in[5];
    const float* b2  = (const float*)d_in[6];
    const float* P1  = (const float*)d_in[7];
    const float* pb1 = (const float*)d_in[8];
    const float* P2  = (const float*)d_in[9];
    const float* pb2 = (const float*)d_in[10];
    const float* P3  = (const float*)d_in[11];
    const float* pb3 = (const float*)d_in[12];
    float* out = (float*)d_out;

    const int* src = ei;
    const int* dst = ei + N_EDGES;

    float *ph1, *pz1, *ph2, *pz2;
    cudaGetSymbolAddress((void**)&ph1, g_h1);
    cudaGetSymbolAddress((void**)&pz1, g_z1);
    cudaGetSymbolAddress((void**)&ph2, g_h2);
    cudaGetSymbolAddress((void**)&pz2, g_z2);
    __nv_bfloat16 *pxhi, *pxlo, *pz1hi, *pz1lo, *pw1hi, *pw1lo, *pw2hi, *pw2lo;
    cudaGetSymbolAddress((void**)&pxhi,  g_xhi);
    cudaGetSymbolAddress((void**)&pxlo,  g_xlo);
    cudaGetSymbolAddress((void**)&pz1hi, g_z1hi);
    cudaGetSymbolAddress((void**)&pz1lo, g_z1lo);
    cudaGetSymbolAddress((void**)&pw1hi, g_w1hi);
    cudaGetSymbolAddress((void**)&pw1lo, g_w1lo);
    cudaGetSymbolAddress((void**)&pw2hi, g_w2hi);
    cudaGetSymbolAddress((void**)&pw2lo, g_w2lo);

    const int SM128 = 2 * 128 * (128 + 8) * 2 + 2 * 128 * 72 * 2;  // 106496
    const int SM64  = 2 * 128 * (64 + 8) * 2  + 2 * 64 * 72 * 2;   //  55296
    const int SMDEC = 2 * 128 * 72 * 2 + 6 * 64 * 72 * 2 + 512;    //  74240
    cudaFuncSetAttribute(mma_gemm_pre<128>, cudaFuncAttributeMaxDynamicSharedMemorySize, SM128);
    cudaFuncSetAttribute(mma_gemm_pre<64>,  cudaFuncAttributeMaxDynamicSharedMemorySize, SM64);
    cudaFuncSetAttribute(decode_kernel,     cudaFuncAttributeMaxDynamicSharedMemorySize, SMDEC);

    // normalization + operand pre-splits
    zero_deg_kernel <<<(N_NODES + 255) / 256, 256>>>();
    count_deg_kernel<<<(N_EDGES + 255) / 256, 256>>>(dst);
    dinv_kernel     <<<(N_NODES + 255) / 256, 256>>>();
    split_kernel<<<(N_NODES * 128 / 4 + 255) / 256, 256>>>(x,  pxhi,  pxlo,  N_NODES * 32);
    split_kernel<<<(128 * 64 / 4 + 255) / 256, 256>>>(W1, pw1hi, pw1lo, 128 * 16);
    split_kernel<<<(64 * 64 / 4 + 255) / 256, 256>>>(W2, pw2hi, pw2lo, 64 * 16);

    const int gbN  = (N_NODES + 127) / 128;   // 391
    const int gbEL = (N_EL    + 127) / 128;   // 782

    // conv layer 1
    mma_gemm_pre<128><<<gbN, 256, SM128>>>(pxhi, pxlo, pw1hi, pw1lo, ph1, pz1, N_NODES);
    scatter_kernel<<<(N_EDGES * 16) / 256, 256>>>(ph1, pz1, src, dst);
    bias_relu_split_kernel<<<(N_NODES * 16) / 256, 256>>>(pz1, b1);

    // conv layer 2 (b2 folded into decode)
    mma_gemm_pre<64><<<gbN, 256, SM64>>>(pz1hi, pz1lo, pw2hi, pw2lo, ph2, pz2, N_NODES);
    scatter_kernel<<<(N_EDGES * 16) / 256, 256>>>(ph2, pz2, src, dst);

    // fused decode
    decode_kernel<<<gbEL, 256, SMDEC>>>(eli, b2, P1, pb1, P2, pb2, P3, pb3, out);
}

// round 5
// speedup vs baseline: 1.7215x; 1.2993x over previous
#include <cuda_runtime.h>
#include <cuda_bf16.h>
#include <cstdint>

#define N_NODES 50000
#define N_EDGES 800000
#define N_EL    100000
#define NSCAN_BLOCKS ((N_NODES + 255) / 256)   // 196

// ---------------- scratch (device globals; no allocation allowed) ----------------
__device__ int   g_degi  [N_NODES];
__device__ int   g_fill  [N_NODES];
__device__ int   g_rowptr[N_NODES + 1];
__device__ int   g_bsum  [256];
__device__ int   g_csr   [N_EDGES];
__device__ float g_dinv[N_NODES];
__device__ float g_h1  [N_NODES * 64];
__device__ float g_h2  [N_NODES * 64];
__device__ float g_z2  [N_NODES * 64];
// pre-split bf16 operand arrays
__device__ __nv_bfloat16 g_xhi [N_NODES * 128];
__device__ __nv_bfloat16 g_xlo [N_NODES * 128];
__device__ __nv_bfloat16 g_z1hi[N_NODES * 64];
__device__ __nv_bfloat16 g_z1lo[N_NODES * 64];
__device__ __nv_bfloat16 g_w1hi[128 * 64];
__device__ __nv_bfloat16 g_w1lo[128 * 64];
__device__ __nv_bfloat16 g_w2hi[64 * 64];
__device__ __nv_bfloat16 g_w2lo[64 * 64];

// ---------------- helpers ----------------
__device__ __forceinline__ uint32_t smem_u32(const void* p) {
    uint32_t a;
    asm("{ .reg .u64 t; cvta.to.shared.u64 t, %1; cvt.u32.u64 %0, t; }" : "=r"(a) : "l"(p));
    return a;
}
__device__ __forceinline__ uint32_t pack_bf16(float x, float y) {
    __nv_bfloat162 t = __floats2bfloat162_rn(x, y);
    return *(uint32_t*)&t;
}
__device__ __forceinline__ float bf_hi(float x) {
    return __bfloat162float(__float2bfloat16_rn(x));
}
__device__ __forceinline__ void cp16(uint32_t dst, const void* src, uint32_t sz) {
    asm volatile("cp.async.ca.shared.global [%0], [%1], 16, %2;"
                 :: "r"(dst), "l"(src), "r"(sz) : "memory");
}
__device__ __forceinline__ void cp_commit_wait() {
    asm volatile("cp.async.commit_group;");
    asm volatile("cp.async.wait_group 0;" ::: "memory");
}
__device__ __forceinline__ void ldsm_x4(uint32_t* r, uint32_t addr) {
    asm volatile("ldmatrix.sync.aligned.m8n8.x4.shared.b16 {%0,%1,%2,%3}, [%4];"
                 : "=r"(r[0]), "=r"(r[1]), "=r"(r[2]), "=r"(r[3]) : "r"(addr));
}
__device__ __forceinline__ void ldsm_x4_t(uint32_t* r, uint32_t addr) {
    asm volatile("ldmatrix.sync.aligned.m8n8.x4.trans.shared.b16 {%0,%1,%2,%3}, [%4];"
                 : "=r"(r[0]), "=r"(r[1]), "=r"(r[2]), "=r"(r[3]) : "r"(addr));
}
__device__ __forceinline__ void mma_bf16(float* d, const uint32_t* a, const uint32_t* b) {
    asm volatile("mma.sync.aligned.m16n8k16.row.col.f32.bf16.bf16.f32 "
                 "{%0,%1,%2,%3}, {%4,%5,%6,%7}, {%8,%9}, {%0,%1,%2,%3};"
                 : "+f"(d[0]), "+f"(d[1]), "+f"(d[2]), "+f"(d[3])
                 : "r"(a[0]), "r"(a[1]), "r"(a[2]), "r"(a[3]), "r"(b[0]), "r"(b[1]));
}

// ---------------- degree / CSR build ----------------
__global__ void zero_cnt_kernel() {
    int i = blockIdx.x * 256 + threadIdx.x;
    if (i < N_NODES) { g_degi[i] = 0; g_fill[i] = 0; }
}
__global__ void count_deg_kernel(const int* __restrict__ dst) {
    int e = blockIdx.x * 256 + threadIdx.x;
    if (e < N_EDGES) atomicAdd(&g_degi[dst[e]], 1);
}
__global__ void dinv_kernel() {
    int i = blockIdx.x * 256 + threadIdx.x;
    if (i < N_NODES) g_dinv[i] = rsqrtf((float)g_degi[i] + 1.0f);  // +1 = self-loop
}
// two-level exclusive scan of g_degi -> g_rowptr
__global__ void scan1_kernel() {
    __shared__ int s[256];
    int i = blockIdx.x * 256 + threadIdx.x;
    int v = (i < N_NODES) ? g_degi[i] : 0;
    s[threadIdx.x] = v;
    __syncthreads();
    #pragma unroll
    for (int o = 1; o < 256; o <<= 1) {
        int t = (threadIdx.x >= o) ? s[threadIdx.x - o] : 0;
        __syncthreads();
        s[threadIdx.x] += t;
        __syncthreads();
    }
    if (i < N_NODES) g_rowptr[i] = s[threadIdx.x] - v;   // exclusive
    if (threadIdx.x == 255) g_bsum[blockIdx.x] = s[255];
}
__global__ void scan2_kernel() {
    __shared__ int s[256];
    int v = (threadIdx.x < NSCAN_BLOCKS) ? g_bsum[threadIdx.x] : 0;
    s[threadIdx.x] = v;
    __syncthreads();
    #pragma unroll
    for (int o = 1; o < 256; o <<= 1) {
        int t = (threadIdx.x >= o) ? s[threadIdx.x - o] : 0;
        __syncthreads();
        s[threadIdx.x] += t;
        __syncthreads();
    }
    g_bsum[threadIdx.x] = s[threadIdx.x] - v;            // exclusive
}
__global__ void scan3_kernel() {
    int i = blockIdx.x * 256 + threadIdx.x;
    if (i < N_NODES) g_rowptr[i] += g_bsum[blockIdx.x];
    if (i == 0) g_rowptr[N_NODES] = N_EDGES;
}
__global__ void fill_csr_kernel(const int* __restrict__ src, const int* __restrict__ dst) {
    int e = blockIdx.x * 256 + threadIdx.x;
    if (e >= N_EDGES) return;
    int d = dst[e];
    int pos = g_rowptr[d] + atomicAdd(&g_fill[d], 1);
    g_csr[pos] = src[e];
}

// ---------------- generic fp32 -> bf16 hi/lo split ----------------
__global__ void split_kernel(const float* __restrict__ in,
                             __nv_bfloat16* __restrict__ hi,
                             __nv_bfloat16* __restrict__ lo, int n4) {
    int i = blockIdx.x * 256 + threadIdx.x;
    if (i >= n4) return;
    float4 v = ((const float4*)in)[i];
    float hx = bf_hi(v.x), hy = bf_hi(v.y), hz = bf_hi(v.z), hw = bf_hi(v.w);
    ((uint2*)hi)[i] = make_uint2(pack_bf16(hx, hy), pack_bf16(hz, hw));
    ((uint2*)lo)[i] = make_uint2(pack_bf16(v.x - hx, v.y - hy), pack_bf16(v.z - hz, v.w - hw));
}

// ---------------- pre-split mma GEMM: C[M,64] = A[M,K] @ B[K,64] ----------------
template<int K>
__global__ __launch_bounds__(256)
void mma_gemm_pre(const __nv_bfloat16* __restrict__ Ahi, const __nv_bfloat16* __restrict__ Alo,
                  const __nv_bfloat16* __restrict__ Bhi, const __nv_bfloat16* __restrict__ Blo,
                  float* __restrict__ C, int M)
{
    constexpr int SA_H = K + 8;
    constexpr int SB_H = 72;
    constexpr int A_HI = 0;
    constexpr int A_LO = 128 * SA_H * 2;
    constexpr int B_HI = 2 * 128 * SA_H * 2;
    constexpr int B_LO = B_HI + K * SB_H * 2;

    extern __shared__ char smem[];
    const uint32_t sbase = smem_u32(smem);
    const int tid  = threadIdx.x;
    const int wid  = tid >> 5;
    const int lane = tid & 31;
    const int row0 = blockIdx.x * 128;

    constexpr int ACH = K / 8;
    #pragma unroll
    for (int idx = tid; idx < 128 * ACH; idx += 256) {
        int r  = idx / ACH;
        int kc = (idx - r * ACH) * 8;
        int row = row0 + r;
        uint32_t sz = (row < M) ? 16u : 0u;
        size_t goff = (size_t)(row < M ? row : 0) * K + kc;
        uint32_t d = sbase + A_HI + (uint32_t)(r * SA_H + kc) * 2;
        cp16(d,                 &Ahi[goff], sz);
        cp16(d + (A_LO - A_HI), &Alo[goff], sz);
    }
    #pragma unroll
    for (int idx = tid; idx < K * 8; idx += 256) {
        int k = idx >> 3, nc = (idx & 7) * 8;
        uint32_t d = sbase + B_HI + (uint32_t)(k * SB_H + nc) * 2;
        cp16(d,                 &Bhi[k * 64 + nc], 16u);
        cp16(d + (B_LO - B_HI), &Blo[k * 64 + nc], 16u);
    }
    cp_commit_wait();
    __syncthreads();

    const int wm = (wid & 3) * 32;
    const int wn = (wid >> 2) * 32;
    const int lrow = lane & 15;
    const int lsel = (lane >> 4) * 8;

    float acc[2][4][4];
    #pragma unroll
    for (int mt = 0; mt < 2; mt++)
        #pragma unroll
        for (int nt = 0; nt < 4; nt++)
            #pragma unroll
            for (int i = 0; i < 4; i++) acc[mt][nt][i] = 0.f;

    #pragma unroll
    for (int k0 = 0; k0 < K; k0 += 16) {
        uint32_t a_hi[2][4], a_lo[2][4];
        #pragma unroll
        for (int mt = 0; mt < 2; mt++) {
            uint32_t off = (uint32_t)((wm + 16 * mt + lrow) * SA_H + k0 + lsel) * 2;
            ldsm_x4(a_hi[mt], sbase + A_HI + off);
            ldsm_x4(a_lo[mt], sbase + A_LO + off);
        }
        uint32_t b_hi[2][4], b_lo[2][4];
        #pragma unroll
        for (int h = 0; h < 2; h++) {
            uint32_t off = (uint32_t)((k0 + lrow) * SB_H + wn + 16 * h + lsel) * 2;
            ldsm_x4_t(b_hi[h], sbase + B_HI + off);
            ldsm_x4_t(b_lo[h], sbase + B_LO + off);
        }
        #pragma unroll
        for (int mt = 0; mt < 2; mt++)
            #pragma unroll
            for (int nt = 0; nt < 4; nt++) {
                const uint32_t* bh = &b_hi[nt >> 1][(nt & 1) * 2];
                const uint32_t* bl = &b_lo[nt >> 1][(nt & 1) * 2];
                mma_bf16(acc[mt][nt], a_hi[mt], bh);
                mma_bf16(acc[mt][nt], a_hi[mt], bl);
                mma_bf16(acc[mt][nt], a_lo[mt], bh);
            }
    }

    const int g  = lane >> 2;
    const int tg = lane & 3;
    #pragma unroll
    for (int mt = 0; mt < 2; mt++)
        #pragma unroll
        for (int rh = 0; rh < 2; rh++) {
            int row = row0 + wm + 16 * mt + g + 8 * rh;
            if (row >= M) continue;
            #pragma unroll
            for (int nt = 0; nt < 4; nt++) {
                int col = wn + 8 * nt + 2 * tg;
                *(float2*)&C[(size_t)row * 64 + col] =
                    make_float2(acc[mt][nt][2 * rh], acc[mt][nt][2 * rh + 1]);
            }
        }
}

// ---------------- CSR gather: z[d] = sum_{s in N(d)} h[s]*dinv[s]*dinv[d] + h[d]*dinv[d]^2 ----
// LAYER1: z1 = relu(z + b1), written as bf16 hi/lo splits only
// !LAYER1: z2 = z (float)
template<bool LAYER1>
__global__ __launch_bounds__(256)
void gather_kernel(const float* __restrict__ h, const float* __restrict__ bias,
                   float* __restrict__ zout)
{
    int node = blockIdx.x * 8 + (threadIdx.x >> 5);   // warp per node
    int lane = threadIdx.x & 31;
    if (node >= N_NODES) return;

    float dd = g_dinv[node];
    const float* hrow = &h[(size_t)node * 64 + lane * 2];
    float2 acc = *(const float2*)hrow;                // self-loop term
    acc.x *= dd * dd; acc.y *= dd * dd;

    int e   = __ldg(&g_rowptr[node]);
    int end = __ldg(&g_rowptr[node + 1]);
    for (; e + 1 < end; e += 2) {
        int s0 = __ldg(&g_csr[e]);
        int s1 = __ldg(&g_csr[e + 1]);
        float w0 = __ldg(&g_dinv[s0]) * dd;
        float w1 = __ldg(&g_dinv[s1]) * dd;
        float2 v0 = *(const float2*)&h[(size_t)s0 * 64 + lane * 2];
        float2 v1 = *(const float2*)&h[(size_t)s1 * 64 + lane * 2];
        acc.x += v0.x * w0; acc.y += v0.y * w0;
        acc.x += v1.x * w1; acc.y += v1.y * w1;
    }
    if (e < end) {
        int s = __ldg(&g_csr[e]);
        float w = __ldg(&g_dinv[s]) * dd;
        float2 v = *(const float2*)&h[(size_t)s * 64 + lane * 2];
        acc.x += v.x * w; acc.y += v.y * w;
    }

    if (LAYER1) {
        float2 b = *(const float2*)&bias[lane * 2];
        float vx = fmaxf(acc.x + b.x, 0.f);
        float vy = fmaxf(acc.y + b.y, 0.f);
        float hx = bf_hi(vx), hy = bf_hi(vy);
        ((uint32_t*)g_z1hi)[node * 32 + lane] = pack_bf16(hx, hy);
        ((uint32_t*)g_z1lo)[node * 32 + lane] = pack_bf16(vx - hx, vy - hy);
    } else {
        *(float2*)&zout[(size_t)node * 64 + lane * 2] = acc;
    }
}

// ---------------- fused decode: ef -> P1+relu -> P2+relu -> P3 dot ----------------
__global__ __launch_bounds__(256)
void decode_kernel(const int* __restrict__ eli, const float* __restrict__ b2,
                   const float* __restrict__ P1, const float* __restrict__ pb1,
                   const float* __restrict__ P2, const float* __restrict__ pb2,
                   const float* __restrict__ P3, const float* __restrict__ pb3,
                   float* __restrict__ out)
{
    constexpr int SA_H = 72, SB_H = 72;
    constexpr int EF_HI = 0;
    constexpr int EF_LO = 128 * SA_H * 2;
    constexpr int P1_HI = 2 * 128 * SA_H * 2;
    constexpr int P1_LO = P1_HI + 64 * SB_H * 2;
    constexpr int P2_HI = P1_LO + 64 * SB_H * 2;
    constexpr int P2_LO = P2_HI + 64 * SB_H * 2;
    constexpr int S_OUT = P2_LO + 64 * SB_H * 2;

    extern __shared__ char smem[];
    const uint32_t sbase = smem_u32(smem);
    const int tid  = threadIdx.x;
    const int wid  = tid >> 5;
    const int lane = tid & 31;
    const int row0 = blockIdx.x * 128;

    if (tid < 128) *(float*)(smem + S_OUT + tid * 4) = 0.f;

    #pragma unroll
    for (int idx = tid; idx < 128 * 16; idx += 256) {
        int pl = idx >> 4, c4 = (idx & 15) << 2;
        int p = row0 + pl;
        float4 r = make_float4(0.f, 0.f, 0.f, 0.f);
        if (p < N_EL) {
            int a = __ldg(&eli[p]);
            int b = __ldg(&eli[N_EL + p]);
            float4 bb = *(const float4*)&b2[c4];
            float4 za = *(const float4*)&g_z2[a * 64 + c4];
            float4 zb = *(const float4*)&g_z2[b * 64 + c4];
            r.x = (za.x + bb.x) * (zb.x + bb.x);
            r.y = (za.y + bb.y) * (zb.y + bb.y);
            r.z = (za.z + bb.z) * (zb.z + bb.z);
            r.w = (za.w + bb.w) * (zb.w + bb.w);
        }
        float hx = bf_hi(r.x), hy = bf_hi(r.y), hz = bf_hi(r.z), hw = bf_hi(r.w);
        uint32_t off = (uint32_t)(pl * SA_H + c4) * 2;
        *(uint2*)(smem + EF_HI + off) = make_uint2(pack_bf16(hx, hy), pack_bf16(hz, hw));
        *(uint2*)(smem + EF_LO + off) = make_uint2(pack_bf16(r.x - hx, r.y - hy),
                                                   pack_bf16(r.z - hz, r.w - hw));
    }
    #pragma unroll
    for (int idx = tid; idx < 64 * 16; idx += 256) {
        int k = idx >> 4, nc = (idx & 15) << 2;
        uint32_t off = (uint32_t)(k * SB_H + nc) * 2;
        float4 v = *(const float4*)&P1[k * 64 + nc];
        float hx = bf_hi(v.x), hy = bf_hi(v.y), hz = bf_hi(v.z), hw = bf_hi(v.w);
        *(uint2*)(smem + P1_HI + off) = make_uint2(pack_bf16(hx, hy), pack_bf16(hz, hw));
        *(uint2*)(smem + P1_LO + off) = make_uint2(pack_bf16(v.x - hx, v.y - hy),
                                                   pack_bf16(v.z - hz, v.w - hw));
        float4 u = *(const float4*)&P2[k * 64 + nc];
        float ux = bf_hi(u.x), uy = bf_hi(u.y), uz = bf_hi(u.z), uw = bf_hi(u.w);
        *(uint2*)(smem + P2_HI + off) = make_uint2(pack_bf16(ux, uy), pack_bf16(uz, uw));
        *(uint2*)(smem + P2_LO + off) = make_uint2(pack_bf16(u.x - ux, u.y - uy),
                                                   pack_bf16(u.z - uz, u.w - uw));
    }
    __syncthreads();

    const int wm = (wid & 3) * 32;
    const int wn = (wid >> 2) * 32;
    const int lrow = lane & 15;
    const int lsel = (lane >> 4) * 8;
    const int g  = lane >> 2;
    const int tg = lane & 3;

    float acc[2][4][4];
    #pragma unroll
    for (int mt = 0; mt < 2; mt++)
        #pragma unroll
        for (int nt = 0; nt < 4; nt++)
            #pragma unroll
            for (int i = 0; i < 4; i++) acc[mt][nt][i] = 0.f;

    #pragma unroll
    for (int k0 = 0; k0 < 64; k0 += 16) {
        uint32_t a_hi[2][4], a_lo[2][4];
        #pragma unroll
        for (int mt = 0; mt < 2; mt++) {
            uint32_t off = (uint32_t)((wm + 16 * mt + lrow) * SA_H + k0 + lsel) * 2;
            ldsm_x4(a_hi[mt], sbase + EF_HI + off);
            ldsm_x4(a_lo[mt], sbase + EF_LO + off);
        }
        uint32_t b_hi[2][4], b_lo[2][4];
        #pragma unroll
        for (int h = 0; h < 2; h++) {
            uint32_t off = (uint32_t)((k0 + lrow) * SB_H + wn + 16 * h + lsel) * 2;
            ldsm_x4_t(b_hi[h], sbase + P1_HI + off);
            ldsm_x4_t(b_lo[h], sbase + P1_LO + off);
        }
        #pragma unroll
        for (int mt = 0; mt < 2; mt++)
            #pragma unroll
            for (int nt = 0; nt < 4; nt++) {
                const uint32_t* bh = &b_hi[nt >> 1][(nt & 1) * 2];
                const uint32_t* bl = &b_lo[nt >> 1][(nt & 1) * 2];
                mma_bf16(acc[mt][nt], a_hi[mt], bh);
                mma_bf16(acc[mt][nt], a_hi[mt], bl);
                mma_bf16(acc[mt][nt], a_lo[mt], bh);
            }
    }
    __syncthreads();

    #pragma unroll
    for (int mt = 0; mt < 2; mt++)
        #pragma unroll
        for (int rh = 0; rh < 2; rh++) {
            int rl = wm + 16 * mt + g + 8 * rh;
            #pragma unroll
            for (int nt = 0; nt < 4; nt++) {
                int col = wn + 8 * nt + 2 * tg;
                float vx = fmaxf(acc[mt][nt][2 * rh]     + __ldg(&pb1[col]),     0.f);
                float vy = fmaxf(acc[mt][nt][2 * rh + 1] + __ldg(&pb1[col + 1]), 0.f);
                float hx = bf_hi(vx), hy = bf_hi(vy);
                uint32_t off = (uint32_t)(rl * SA_H + col) * 2;
                *(uint32_t*)(smem + EF_HI + off) = pack_bf16(hx, hy);
                *(uint32_t*)(smem + EF_LO + off) = pack_bf16(vx - hx, vy - hy);
            }
        }
    __syncthreads();

    #pragma unroll
    for (int mt = 0; mt < 2; mt++)
        #pragma unroll
        for (int nt = 0; nt < 4; nt++)
            #pragma unroll
            for (int i = 0; i < 4; i++) acc[mt][nt][i] = 0.f;

    #pragma unroll
    for (int k0 = 0; k0 < 64; k0 += 16) {
        uint32_t a_hi[2][4], a_lo[2][4];
        #pragma unroll
        for (int mt = 0; mt < 2; mt++) {
            uint32_t off = (uint32_t)((wm + 16 * mt + lrow) * SA_H + k0 + lsel) * 2;
            ldsm_x4(a_hi[mt], sbase + EF_HI + off);
            ldsm_x4(a_lo[mt], sbase + EF_LO + off);
        }
        uint32_t b_hi[2][4], b_lo[2][4];
        #pragma unroll
        for (int h = 0; h < 2; h++) {
            uint32_t off = (uint32_t)((k0 + lrow) * SB_H + wn + 16 * h + lsel) * 2;
            ldsm_x4_t(b_hi[h], sbase + P2_HI + off);
            ldsm_x4_t(b_lo[h], sbase + P2_LO + off);
        }
        #pragma unroll
        for (int mt = 0; mt < 2; mt++)
            #pragma unroll
            for (int nt = 0; nt < 4; nt++) {
                const uint32_t* bh = &b_hi[nt >> 1][(nt & 1) * 2];
                const uint32_t* bl = &b_lo[nt >> 1][(nt & 1) * 2];
                mma_bf16(acc[mt][nt], a_hi[mt], bh);
                mma_bf16(acc[mt][nt], a_hi[mt], bl);
                mma_bf16(acc[mt][nt], a_lo[mt], bh);
            }
    }

    #pragma unroll
    for (int mt = 0; mt < 2; mt++)
        #pragma unroll
        for (int rh = 0; rh < 2; rh++) {
            float s = 0.f;
            #pragma unroll
            for (int nt = 0; nt < 4; nt++) {
                int col = wn + 8 * nt + 2 * tg;
                float vx = fmaxf(acc[mt][nt][2 * rh]     + __ldg(&pb2[col]),     0.f);
                float vy = fmaxf(acc[mt][nt][2 * rh + 1] + __ldg(&pb2[col + 1]), 0.f);
                s += vx * __ldg(&P3[col]) + vy * __ldg(&P3[col + 1]);
            }
            s += __shfl_xor_sync(0xffffffffu, s, 1);
            s += __shfl_xor_sync(0xffffffffu, s, 2);
            if (tg == 0) {
                int rl = wm + 16 * mt + g + 8 * rh;
                atomicAdd((float*)(smem + S_OUT) + rl, s);
            }
        }
    __syncthreads();
    if (tid < 128) {
        int p = row0 + tid;
        if (p < N_EL) out[p] = *(float*)(smem + S_OUT + tid * 4) + __ldg(&pb3[0]);
    }
}

// ---------------- launcher ----------------
extern "C" void kernel_launch(void* const* d_in, const int* in_sizes, int n_in,
                              void* d_out, int out_size)
{
    const float* x   = (const float*)d_in[0];
    const int*   ei  = (const int*)  d_in[1];
    const int*   eli = (const int*)  d_in[2];
    const float* W1  = (const float*)d_in[3];
    const float* b1  = (const float*)d_in[4];
    const float* W2  = (const float*)d_in[5];
    const float* b2  = (const float*)d_in[6];
    const float* P1  = (const float*)d_in[7];
    const float* pb1 = (const float*)d_in[8];
    const float* P2  = (const float*)d_in[9];
    const float* pb2 = (const float*)d_in[10];
    const float* P3  = (const float*)d_in[11];
    const float* pb3 = (const float*)d_in[12];
    float* out = (float*)d_out;

    const int* src = ei;
    const int* dst = ei + N_EDGES;

    float *ph1, *ph2, *pz2;
    cudaGetSymbolAddress((void**)&ph1, g_h1);
    cudaGetSymbolAddress((void**)&ph2, g_h2);
    cudaGetSymbolAddress((void**)&pz2, g_z2);
    __nv_bfloat16 *pxhi, *pxlo, *pz1hi, *pz1lo, *pw1hi, *pw1lo, *pw2hi, *pw2lo;
    cudaGetSymbolAddress((void**)&pxhi,  g_xhi);
    cudaGetSymbolAddress((void**)&pxlo,  g_xlo);
    cudaGetSymbolAddress((void**)&pz1hi, g_z1hi);
    cudaGetSymbolAddress((void**)&pz1lo, g_z1lo);
    cudaGetSymbolAddress((void**)&pw1hi, g_w1hi);
    cudaGetSymbolAddress((void**)&pw1lo, g_w1lo);
    cudaGetSymbolAddress((void**)&pw2hi, g_w2hi);
    cudaGetSymbolAddress((void**)&pw2lo, g_w2lo);

    const int SM128 = 2 * 128 * (128 + 8) * 2 + 2 * 128 * 72 * 2;  // 106496
    const int SM64  = 2 * 128 * (64 + 8) * 2  + 2 * 64 * 72 * 2;   //  55296
    const int SMDEC = 2 * 128 * 72 * 2 + 6 * 64 * 72 * 2 + 512;    //  74240
    cudaFuncSetAttribute(mma_gemm_pre<128>, cudaFuncAttributeMaxDynamicSharedMemorySize, SM128);
    cudaFuncSetAttribute(mma_gemm_pre<64>,  cudaFuncAttributeMaxDynamicSharedMemorySize, SM64);
    cudaFuncSetAttribute(decode_kernel,     cudaFuncAttributeMaxDynamicSharedMemorySize, SMDEC);

    const int gbNode = (N_NODES + 255) / 256;
    const int gbEdge = (N_EDGES + 255) / 256;

    // CSR build + normalization
    zero_cnt_kernel <<<gbNode, 256>>>();
    count_deg_kernel<<<gbEdge, 256>>>(dst);
    dinv_kernel     <<<gbNode, 256>>>();
    scan1_kernel    <<<NSCAN_BLOCKS, 256>>>();
    scan2_kernel    <<<1, 256>>>();
    scan3_kernel    <<<NSCAN_BLOCKS, 256>>>();
    fill_csr_kernel <<<gbEdge, 256>>>(src, dst);

    // operand pre-splits
    split_kernel<<<(N_NODES * 32 + 255) / 256, 256>>>(x,  pxhi,  pxlo,  N_NODES * 32);
    split_kernel<<<(128 * 16 + 255) / 256, 256>>>(W1, pw1hi, pw1lo, 128 * 16);
    split_kernel<<<(64 * 16 + 255) / 256, 256>>>(W2, pw2hi, pw2lo, 64 * 16);

    const int gbN  = (N_NODES + 127) / 128;   // 391
    const int gbEL = (N_EL    + 127) / 128;   // 782
    const int gbG  = (N_NODES + 7) / 8;       // 6250

    // conv layer 1: h1 = x@W1 ; gather (+bias+relu+split fused)
    mma_gemm_pre<128><<<gbN, 256, SM128>>>(pxhi, pxlo, pw1hi, pw1lo, ph1, N_NODES);
    gather_kernel<true><<<gbG, 256>>>(ph1, b1, nullptr);

    // conv layer 2: h2 = z1@W2 ; gather (b2 folded into decode)
    mma_gemm_pre<64><<<gbN, 256, SM64>>>(pz1hi, pz1lo, pw2hi, pw2lo, ph2, N_NODES);
    gather_kernel<false><<<gbG, 256>>>(ph2, nullptr, pz2);

    // fused decode
    decode_kernel<<<gbEL, 256, SMDEC>>>(eli, b2, P1, pb1, P2, pb2, P3, pb3, out);
}

// round 6
// speedup vs baseline: 1.8036x; 1.0477x over previous
#include <cuda_runtime.h>
#include <cuda_bf16.h>
#include <cstdint>

#define N_NODES 50000
#define N_EDGES 800000
#define N_EL    100000
#define NSCAN_BLOCKS ((N_NODES + 255) / 256)   // 196

// ---------------- scratch (device globals; no allocation allowed) ----------------
__device__ int   g_degi  [N_NODES];
__device__ int   g_rowptr[N_NODES + 1];
__device__ int   g_bsum  [256];
__device__ int   g_csr   [N_EDGES];
__device__ float g_dinv[N_NODES];
__device__ float g_h1  [N_NODES * 64];
__device__ float g_h2  [N_NODES * 64];
__device__ float g_z2  [N_NODES * 64];
// pre-split bf16 operand arrays
__device__ __nv_bfloat16 g_xhi [N_NODES * 128];
__device__ __nv_bfloat16 g_xlo [N_NODES * 128];
__device__ __nv_bfloat16 g_z1hi[N_NODES * 64];
__device__ __nv_bfloat16 g_z1lo[N_NODES * 64];
__device__ __nv_bfloat16 g_w1hi[128 * 64];
__device__ __nv_bfloat16 g_w1lo[128 * 64];
__device__ __nv_bfloat16 g_w2hi[64 * 64];
__device__ __nv_bfloat16 g_w2lo[64 * 64];

// ---------------- helpers ----------------
__device__ __forceinline__ uint32_t smem_u32(const void* p) {
    uint32_t a;
    asm("{ .reg .u64 t; cvta.to.shared.u64 t, %1; cvt.u32.u64 %0, t; }" : "=r"(a) : "l"(p));
    return a;
}
__device__ __forceinline__ uint32_t pack_bf16(float x, float y) {
    __nv_bfloat162 t = __floats2bfloat162_rn(x, y);
    return *(uint32_t*)&t;
}
__device__ __forceinline__ float bf_hi(float x) {
    return __bfloat162float(__float2bfloat16_rn(x));
}
__device__ __forceinline__ void cp16(uint32_t dst, const void* src, uint32_t sz) {
    asm volatile("cp.async.ca.shared.global [%0], [%1], 16, %2;"
                 :: "r"(dst), "l"(src), "r"(sz) : "memory");
}
__device__ __forceinline__ void cp_commit_wait() {
    asm volatile("cp.async.commit_group;");
    asm volatile("cp.async.wait_group 0;" ::: "memory");
}
__device__ __forceinline__ void ldsm_x4(uint32_t* r, uint32_t addr) {
    asm volatile("ldmatrix.sync.aligned.m8n8.x4.shared.b16 {%0,%1,%2,%3}, [%4];"
                 : "=r"(r[0]), "=r"(r[1]), "=r"(r[2]), "=r"(r[3]) : "r"(addr));
}
__device__ __forceinline__ void ldsm_x4_t(uint32_t* r, uint32_t addr) {
    asm volatile("ldmatrix.sync.aligned.m8n8.x4.trans.shared.b16 {%0,%1,%2,%3}, [%4];"
                 : "=r"(r[0]), "=r"(r[1]), "=r"(r[2]), "=r"(r[3]) : "r"(addr));
}
__device__ __forceinline__ void mma_bf16(float* d, const uint32_t* a, const uint32_t* b) {
    asm volatile("mma.sync.aligned.m16n8k16.row.col.f32.bf16.bf16.f32 "
                 "{%0,%1,%2,%3}, {%4,%5,%6,%7}, {%8,%9}, {%0,%1,%2,%3};"
                 : "+f"(d[0]), "+f"(d[1]), "+f"(d[2]), "+f"(d[3])
                 : "r"(a[0]), "r"(a[1]), "r"(a[2]), "r"(a[3]), "r"(b[0]), "r"(b[1]));
}
__device__ __forceinline__ void split_store(const float* __restrict__ in,
                                            __nv_bfloat16* __restrict__ hi,
                                            __nv_bfloat16* __restrict__ lo, int i) {
    float4 v = ((const float4*)in)[i];
    float hx = bf_hi(v.x), hy = bf_hi(v.y), hz = bf_hi(v.z), hw = bf_hi(v.w);
    ((uint2*)hi)[i] = make_uint2(pack_bf16(hx, hy), pack_bf16(hz, hw));
    ((uint2*)lo)[i] = make_uint2(pack_bf16(v.x - hx, v.y - hy), pack_bf16(v.z - hz, v.w - hw));
}

// ---------------- prep: zero degi + split x, W1, W2 (range-dispatched) ----------------
#define ZB NSCAN_BLOCKS                     // 196 blocks zero degi
#define XB ((N_NODES * 32 + 255) / 256)     // 6250 blocks split x
#define W1B ((128 * 16 + 255) / 256)        // 8 blocks
#define W2B ((64 * 16 + 255) / 256)         // 4 blocks
__global__ void prep_kernel(const float* __restrict__ x, const float* __restrict__ W1,
                            const float* __restrict__ W2) {
    int b = blockIdx.x;
    if (b < ZB) {
        int i = b * 256 + threadIdx.x;
        if (i < N_NODES) g_degi[i] = 0;
    } else if (b < ZB + XB) {
        int i = (b - ZB) * 256 + threadIdx.x;
        if (i < N_NODES * 32) split_store(x, g_xhi, g_xlo, i);
    } else if (b < ZB + XB + W1B) {
        int i = (b - ZB - XB) * 256 + threadIdx.x;
        if (i < 128 * 16) split_store(W1, g_w1hi, g_w1lo, i);
    } else {
        int i = (b - ZB - XB - W1B) * 256 + threadIdx.x;
        if (i < 64 * 16) split_store(W2, g_w2hi, g_w2lo, i);
    }
}

__global__ void count_deg_kernel(const int* __restrict__ dst) {
    int e = blockIdx.x * 256 + threadIdx.x;
    if (e < N_EDGES) atomicAdd(&g_degi[dst[e]], 1);
}

// ---------------- warp-shuffle scans (exclusive) + fused dinv ----------------
__device__ __forceinline__ int warp_incl_scan(int v, int lane) {
    #pragma unroll
    for (int o = 1; o < 32; o <<= 1) {
        int t = __shfl_up_sync(0xffffffffu, v, o);
        if (lane >= o) v += t;
    }
    return v;
}
__global__ void scan1_kernel() {
    __shared__ int wsum[8];
    int i = blockIdx.x * 256 + threadIdx.x;
    int lane = threadIdx.x & 31, w = threadIdx.x >> 5;
    int d = (i < N_NODES) ? g_degi[i] : 0;
    if (i < N_NODES) g_dinv[i] = rsqrtf((float)d + 1.0f);   // fused (+1 = self-loop)
    int s = warp_incl_scan(d, lane);
    if (lane == 31) wsum[w] = s;
    __syncthreads();
    if (w == 0) {
        int ws = (lane < 8) ? wsum[lane] : 0;
        ws = warp_incl_scan(ws, lane);
        if (lane < 8) wsum[lane] = ws;
    }
    __syncthreads();
    int base = (w > 0) ? wsum[w - 1] : 0;
    if (i < N_NODES) g_rowptr[i] = base + s - d;            // exclusive
    if (threadIdx.x == 255) g_bsum[blockIdx.x] = base + s;
}
__global__ void scan2_kernel() {
    __shared__ int wsum[8];
    int lane = threadIdx.x & 31, w = threadIdx.x >> 5;
    int v = (threadIdx.x < NSCAN_BLOCKS) ? g_bsum[threadIdx.x] : 0;
    int s = warp_incl_scan(v, lane);
    if (lane == 31) wsum[w] = s;
    __syncthreads();
    if (w == 0) {
        int ws = (lane < 8) ? wsum[lane] : 0;
        ws = warp_incl_scan(ws, lane);
        if (lane < 8) wsum[lane] = ws;
    }
    __syncthreads();
    int base = (w > 0) ? wsum[w - 1] : 0;
    g_bsum[threadIdx.x] = base + s - v;                     // exclusive
}
__global__ void scan3_kernel() {
    int i = blockIdx.x * 256 + threadIdx.x;
    if (i < N_NODES) g_rowptr[i] += g_bsum[blockIdx.x];
    if (i == 0) g_rowptr[N_NODES] = N_EDGES;
}
// fill via atomicSub on degi (degree counts dead after scan1)
__global__ void fill_csr_kernel(const int* __restrict__ src, const int* __restrict__ dst) {
    int e = blockIdx.x * 256 + threadIdx.x;
    if (e >= N_EDGES) return;
    int d = dst[e];
    int old = atomicSub(&g_degi[d], 1);
    g_csr[g_rowptr[d] + old - 1] = src[e];
}

// ---------------- pre-split mma GEMM: C[M,64] = A[M,K] @ B[K,64] ----------------
template<int K>
__global__ __launch_bounds__(256)
void mma_gemm_pre(const __nv_bfloat16* __restrict__ Ahi, const __nv_bfloat16* __restrict__ Alo,
                  const __nv_bfloat16* __restrict__ Bhi, const __nv_bfloat16* __restrict__ Blo,
                  float* __restrict__ C, int M)
{
    constexpr int SA_H = K + 8;
    constexpr int SB_H = 72;
    constexpr int A_HI = 0;
    constexpr int A_LO = 128 * SA_H * 2;
    constexpr int B_HI = 2 * 128 * SA_H * 2;
    constexpr int B_LO = B_HI + K * SB_H * 2;

    extern __shared__ char smem[];
    const uint32_t sbase = smem_u32(smem);
    const int tid  = threadIdx.x;
    const int wid  = tid >> 5;
    const int lane = tid & 31;
    const int row0 = blockIdx.x * 128;

    constexpr int ACH = K / 8;
    #pragma unroll
    for (int idx = tid; idx < 128 * ACH; idx += 256) {
        int r  = idx / ACH;
        int kc = (idx - r * ACH) * 8;
        int row = row0 + r;
        uint32_t sz = (row < M) ? 16u : 0u;
        size_t goff = (size_t)(row < M ? row : 0) * K + kc;
        uint32_t d = sbase + A_HI + (uint32_t)(r * SA_H + kc) * 2;
        cp16(d,                 &Ahi[goff], sz);
        cp16(d + (A_LO - A_HI), &Alo[goff], sz);
    }
    #pragma unroll
    for (int idx = tid; idx < K * 8; idx += 256) {
        int k = idx >> 3, nc = (idx & 7) * 8;
        uint32_t d = sbase + B_HI + (uint32_t)(k * SB_H + nc) * 2;
        cp16(d,                 &Bhi[k * 64 + nc], 16u);
        cp16(d + (B_LO - B_HI), &Blo[k * 64 + nc], 16u);
    }
    cp_commit_wait();
    __syncthreads();

    const int wm = (wid & 3) * 32;
    const int wn = (wid >> 2) * 32;
    const int lrow = lane & 15;
    const int lsel = (lane >> 4) * 8;

    float acc[2][4][4];
    #pragma unroll
    for (int mt = 0; mt < 2; mt++)
        #pragma unroll
        for (int nt = 0; nt < 4; nt++)
            #pragma unroll
            for (int i = 0; i < 4; i++) acc[mt][nt][i] = 0.f;

    #pragma unroll
    for (int k0 = 0; k0 < K; k0 += 16) {
        uint32_t a_hi[2][4], a_lo[2][4];
        #pragma unroll
        for (int mt = 0; mt < 2; mt++) {
            uint32_t off = (uint32_t)((wm + 16 * mt + lrow) * SA_H + k0 + lsel) * 2;
            ldsm_x4(a_hi[mt], sbase + A_HI + off);
            ldsm_x4(a_lo[mt], sbase + A_LO + off);
        }
        uint32_t b_hi[2][4], b_lo[2][4];
        #pragma unroll
        for (int h = 0; h < 2; h++) {
            uint32_t off = (uint32_t)((k0 + lrow) * SB_H + wn + 16 * h + lsel) * 2;
            ldsm_x4_t(b_hi[h], sbase + B_HI + off);
            ldsm_x4_t(b_lo[h], sbase + B_LO + off);
        }
        #pragma unroll
        for (int mt = 0; mt < 2; mt++)
            #pragma unroll
            for (int nt = 0; nt < 4; nt++) {
                const uint32_t* bh = &b_hi[nt >> 1][(nt & 1) * 2];
                const uint32_t* bl = &b_lo[nt >> 1][(nt & 1) * 2];
                mma_bf16(acc[mt][nt], a_hi[mt], bh);
                mma_bf16(acc[mt][nt], a_hi[mt], bl);
                mma_bf16(acc[mt][nt], a_lo[mt], bh);
            }
    }

    const int g  = lane >> 2;
    const int tg = lane & 3;
    #pragma unroll
    for (int mt = 0; mt < 2; mt++)
        #pragma unroll
        for (int rh = 0; rh < 2; rh++) {
            int row = row0 + wm + 16 * mt + g + 8 * rh;
            if (row >= M) continue;
            #pragma unroll
            for (int nt = 0; nt < 4; nt++) {
                int col = wn + 8 * nt + 2 * tg;
                *(float2*)&C[(size_t)row * 64 + col] =
                    make_float2(acc[mt][nt][2 * rh], acc[mt][nt][2 * rh + 1]);
            }
        }
}

// ---------------- CSR gather, 4-wide unrolled ----------------
template<bool LAYER1>
__global__ __launch_bounds__(256)
void gather_kernel(const float* __restrict__ h, const float* __restrict__ bias,
                   float* __restrict__ zout)
{
    int node = blockIdx.x * 8 + (threadIdx.x >> 5);   // warp per node
    int lane = threadIdx.x & 31;
    if (node >= N_NODES) return;

    float dd = g_dinv[node];
    float2 a0 = *(const float2*)&h[(size_t)node * 64 + lane * 2];   // self-loop
    a0.x *= dd * dd; a0.y *= dd * dd;
    float2 a1 = make_float2(0.f, 0.f);
    float2 a2 = make_float2(0.f, 0.f);
    float2 a3 = make_float2(0.f, 0.f);

    int e   = __ldg(&g_rowptr[node]);
    int end = __ldg(&g_rowptr[node + 1]);
    for (; e + 3 < end; e += 4) {
        int s0 = __ldg(&g_csr[e]);
        int s1 = __ldg(&g_csr[e + 1]);
        int s2 = __ldg(&g_csr[e + 2]);
        int s3 = __ldg(&g_csr[e + 3]);
        float w0 = __ldg(&g_dinv[s0]) * dd;
        float w1 = __ldg(&g_dinv[s1]) * dd;
        float w2 = __ldg(&g_dinv[s2]) * dd;
        float w3 = __ldg(&g_dinv[s3]) * dd;
        float2 v0 = *(const float2*)&h[(size_t)s0 * 64 + lane * 2];
        float2 v1 = *(const float2*)&h[(size_t)s1 * 64 + lane * 2];
        float2 v2 = *(const float2*)&h[(size_t)s2 * 64 + lane * 2];
        float2 v3 = *(const float2*)&h[(size_t)s3 * 64 + lane * 2];
        a0.x += v0.x * w0; a0.y += v0.y * w0;
        a1.x += v1.x * w1; a1.y += v1.y * w1;
        a2.x += v2.x * w2; a2.y += v2.y * w2;
        a3.x += v3.x * w3; a3.y += v3.y * w3;
    }
    for (; e < end; e++) {
        int s = __ldg(&g_csr[e]);
        float w = __ldg(&g_dinv[s]) * dd;
        float2 v = *(const float2*)&h[(size_t)s * 64 + lane * 2];
        a0.x += v.x * w; a0.y += v.y * w;
    }
    float2 acc = make_float2((a0.x + a1.x) + (a2.x + a3.x),
                             (a0.y + a1.y) + (a2.y + a3.y));

    if (LAYER1) {
        float2 b = *(const float2*)&bias[lane * 2];
        float vx = fmaxf(acc.x + b.x, 0.f);
        float vy = fmaxf(acc.y + b.y, 0.f);
        float hx = bf_hi(vx), hy = bf_hi(vy);
        ((uint32_t*)g_z1hi)[node * 32 + lane] = pack_bf16(hx, hy);
        ((uint32_t*)g_z1lo)[node * 32 + lane] = pack_bf16(vx - hx, vy - hy);
    } else {
        *(float2*)&zout[(size_t)node * 64 + lane * 2] = acc;
    }
}

// ---------------- fused decode: ef -> P1+relu -> P2+relu -> P3 dot ----------------
__global__ __launch_bounds__(256)
void decode_kernel(const int* __restrict__ eli, const float* __restrict__ b2,
                   const float* __restrict__ P1, const float* __restrict__ pb1,
                   const float* __restrict__ P2, const float* __restrict__ pb2,
                   const float* __restrict__ P3, const float* __restrict__ pb3,
                   float* __restrict__ out)
{
    constexpr int SA_H = 72, SB_H = 72;
    constexpr int EF_HI = 0;
    constexpr int EF_LO = 128 * SA_H * 2;
    constexpr int P1_HI = 2 * 128 * SA_H * 2;
    constexpr int P1_LO = P1_HI + 64 * SB_H * 2;
    constexpr int P2_HI = P1_LO + 64 * SB_H * 2;
    constexpr int P2_LO = P2_HI + 64 * SB_H * 2;
    constexpr int S_OUT = P2_LO + 64 * SB_H * 2;

    extern __shared__ char smem[];
    const uint32_t sbase = smem_u32(smem);
    const int tid  = threadIdx.x;
    const int wid  = tid >> 5;
    const int lane = tid & 31;
    const int row0 = blockIdx.x * 128;

    if (tid < 128) *(float*)(smem + S_OUT + tid * 4) = 0.f;

    #pragma unroll
    for (int idx = tid; idx < 128 * 16; idx += 256) {
        int pl = idx >> 4, c4 = (idx & 15) << 2;
        int p = row0 + pl;
        float4 r = make_float4(0.f, 0.f, 0.f, 0.f);
        if (p < N_EL) {
            int a = __ldg(&eli[p]);
            int b = __ldg(&eli[N_EL + p]);
            float4 bb = *(const float4*)&b2[c4];
            float4 za = *(const float4*)&g_z2[a * 64 + c4];
            float4 zb = *(const float4*)&g_z2[b * 64 + c4];
            r.x = (za.x + bb.x) * (zb.x + bb.x);
            r.y = (za.y + bb.y) * (zb.y + bb.y);
            r.z = (za.z + bb.z) * (zb.z + bb.z);
            r.w = (za.w + bb.w) * (zb.w + bb.w);
        }
        float hx = bf_hi(r.x), hy = bf_hi(r.y), hz = bf_hi(r.z), hw = bf_hi(r.w);
        uint32_t off = (uint32_t)(pl * SA_H + c4) * 2;
        *(uint2*)(smem + EF_HI + off) = make_uint2(pack_bf16(hx, hy), pack_bf16(hz, hw));
        *(uint2*)(smem + EF_LO + off) = make_uint2(pack_bf16(r.x - hx, r.y - hy),
                                                   pack_bf16(r.z - hz, r.w - hw));
    }
    #pragma unroll
    for (int idx = tid; idx < 64 * 16; idx += 256) {
        int k = idx >> 4, nc = (idx & 15) << 2;
        uint32_t off = (uint32_t)(k * SB_H + nc) * 2;
        float4 v = *(const float4*)&P1[k * 64 + nc];
        float hx = bf_hi(v.x), hy = bf_hi(v.y), hz = bf_hi(v.z), hw = bf_hi(v.w);
        *(uint2*)(smem + P1_HI + off) = make_uint2(pack_bf16(hx, hy), pack_bf16(hz, hw));
        *(uint2*)(smem + P1_LO + off) = make_uint2(pack_bf16(v.x - hx, v.y - hy),
                                                   pack_bf16(v.z - hz, v.w - hw));
        float4 u = *(const float4*)&P2[k * 64 + nc];
        float ux = bf_hi(u.x), uy = bf_hi(u.y), uz = bf_hi(u.z), uw = bf_hi(u.w);
        *(uint2*)(smem + P2_HI + off) = make_uint2(pack_bf16(ux, uy), pack_bf16(uz, uw));
        *(uint2*)(smem + P2_LO + off) = make_uint2(pack_bf16(u.x - ux, u.y - uy),
                                                   pack_bf16(u.z - uz, u.w - uw));
    }
    __syncthreads();

    const int wm = (wid & 3) * 32;
    const int wn = (wid >> 2) * 32;
    const int lrow = lane & 15;
    const int lsel = (lane >> 4) * 8;
    const int g  = lane >> 2;
    const int tg = lane & 3;

    float acc[2][4][4];
    #pragma unroll
    for (int mt = 0; mt < 2; mt++)
        #pragma unroll
        for (int nt = 0; nt < 4; nt++)
            #pragma unroll
            for (int i = 0; i < 4; i++) acc[mt][nt][i] = 0.f;

    #pragma unroll
    for (int k0 = 0; k0 < 64; k0 += 16) {
        uint32_t a_hi[2][4], a_lo[2][4];
        #pragma unroll
        for (int mt = 0; mt < 2; mt++) {
            uint32_t off = (uint32_t)((wm + 16 * mt + lrow) * SA_H + k0 + lsel) * 2;
            ldsm_x4(a_hi[mt], sbase + EF_HI + off);
            ldsm_x4(a_lo[mt], sbase + EF_LO + off);
        }
        uint32_t b_hi[2][4], b_lo[2][4];
        #pragma unroll
        for (int h = 0; h < 2; h++) {
            uint32_t off = (uint32_t)((k0 + lrow) * SB_H + wn + 16 * h + lsel) * 2;
            ldsm_x4_t(b_hi[h], sbase + P1_HI + off);
            ldsm_x4_t(b_lo[h], sbase + P1_LO + off);
        }
        #pragma unroll
        for (int mt = 0; mt < 2; mt++)
            #pragma unroll
            for (int nt = 0; nt < 4; nt++) {
                const uint32_t* bh = &b_hi[nt >> 1][(nt & 1) * 2];
                const uint32_t* bl = &b_lo[nt >> 1][(nt & 1) * 2];
                mma_bf16(acc[mt][nt], a_hi[mt], bh);
                mma_bf16(acc[mt][nt], a_hi[mt], bl);
                mma_bf16(acc[mt][nt], a_lo[mt], bh);
            }
    }
    __syncthreads();

    #pragma unroll
    for (int mt = 0; mt < 2; mt++)
        #pragma unroll
        for (int rh = 0; rh < 2; rh++) {
            int rl = wm + 16 * mt + g + 8 * rh;
            #pragma unroll
            for (int nt = 0; nt < 4; nt++) {
                int col = wn + 8 * nt + 2 * tg;
                float vx = fmaxf(acc[mt][nt][2 * rh]     + __ldg(&pb1[col]),     0.f);
                float vy = fmaxf(acc[mt][nt][2 * rh + 1] + __ldg(&pb1[col + 1]), 0.f);
                float hx = bf_hi(vx), hy = bf_hi(vy);
                uint32_t off = (uint32_t)(rl * SA_H + col) * 2;
                *(uint32_t*)(smem + EF_HI + off) = pack_bf16(hx, hy);
                *(uint32_t*)(smem + EF_LO + off) = pack_bf16(vx - hx, vy - hy);
            }
        }
    __syncthreads();

    #pragma unroll
    for (int mt = 0; mt < 2; mt++)
        #pragma unroll
        for (int nt = 0; nt < 4; nt++)
            #pragma unroll
            for (int i = 0; i < 4; i++) acc[mt][nt][i] = 0.f;

    #pragma unroll
    for (int k0 = 0; k0 < 64; k0 += 16) {
        uint32_t a_hi[2][4], a_lo[2][4];
        #pragma unroll
        for (int mt = 0; mt < 2; mt++) {
            uint32_t off = (uint32_t)((wm + 16 * mt + lrow) * SA_H + k0 + lsel) * 2;
            ldsm_x4(a_hi[mt], sbase + EF_HI + off);
            ldsm_x4(a_lo[mt], sbase + EF_LO + off);
        }
        uint32_t b_hi[2][4], b_lo[2][4];
        #pragma unroll
        for (int h = 0; h < 2; h++) {
            uint32_t off = (uint32_t)((k0 + lrow) * SB_H + wn + 16 * h + lsel) * 2;
            ldsm_x4_t(b_hi[h], sbase + P2_HI + off);
            ldsm_x4_t(b_lo[h], sbase + P2_LO + off);
        }
        #pragma unroll
        for (int mt = 0; mt < 2; mt++)
            #pragma unroll
            for (int nt = 0; nt < 4; nt++) {
                const uint32_t* bh = &b_hi[nt >> 1][(nt & 1) * 2];
                const uint32_t* bl = &b_lo[nt >> 1][(nt & 1) * 2];
                mma_bf16(acc[mt][nt], a_hi[mt], bh);
                mma_bf16(acc[mt][nt], a_hi[mt], bl);
                mma_bf16(acc[mt][nt], a_lo[mt], bh);
            }
    }

    #pragma unroll
    for (int mt = 0; mt < 2; mt++)
        #pragma unroll
        for (int rh = 0; rh < 2; rh++) {
            float s = 0.f;
            #pragma unroll
            for (int nt = 0; nt < 4; nt++) {
                int col = wn + 8 * nt + 2 * tg;
                float vx = fmaxf(acc[mt][nt][2 * rh]     + __ldg(&pb2[col]),     0.f);
                float vy = fmaxf(acc[mt][nt][2 * rh + 1] + __ldg(&pb2[col + 1]), 0.f);
                s += vx * __ldg(&P3[col]) + vy * __ldg(&P3[col + 1]);
            }
            s += __shfl_xor_sync(0xffffffffu, s, 1);
            s += __shfl_xor_sync(0xffffffffu, s, 2);
            if (tg == 0) {
                int rl = wm + 16 * mt + g + 8 * rh;
                atomicAdd((float*)(smem + S_OUT) + rl, s);
            }
        }
    __syncthreads();
    if (tid < 128) {
        int p = row0 + tid;
        if (p < N_EL) out[p] = *(float*)(smem + S_OUT + tid * 4) + __ldg(&pb3[0]);
    }
}

// ---------------- launcher ----------------
extern "C" void kernel_launch(void* const* d_in, const int* in_sizes, int n_in,
                              void* d_out, int out_size)
{
    const float* x   = (const float*)d_in[0];
    const int*   ei  = (const int*)  d_in[1];
    const int*   eli = (const int*)  d_in[2];
    const float* W1  = (const float*)d_in[3];
    const float* b1  = (const float*)d_in[4];
    const float* W2  = (const float*)d_in[5];
    const float* b2  = (const float*)d_in[6];
    const float* P1  = (const float*)d_in[7];
    const float* pb1 = (const float*)d_in[8];
    const float* P2  = (const float*)d_in[9];
    const float* pb2 = (const float*)d_in[10];
    const float* P3  = (const float*)d_in[11];
    const float* pb3 = (const float*)d_in[12];
    float* out = (float*)d_out;

    const int* src = ei;
    const int* dst = ei + N_EDGES;

    float *ph1, *ph2, *pz2;
    cudaGetSymbolAddress((void**)&ph1, g_h1);
    cudaGetSymbolAddress((void**)&ph2, g_h2);
    cudaGetSymbolAddress((void**)&pz2, g_z2);
    __nv_bfloat16 *pxhi, *pxlo, *pz1hi, *pz1lo, *pw1hi, *pw1lo, *pw2hi, *pw2lo;
    cudaGetSymbolAddress((void**)&pxhi,  g_xhi);
    cudaGetSymbolAddress((void**)&pxlo,  g_xlo);
    cudaGetSymbolAddress((void**)&pz1hi, g_z1hi);
    cudaGetSymbolAddress((void**)&pz1lo, g_z1lo);
    cudaGetSymbolAddress((void**)&pw1hi, g_w1hi);
    cudaGetSymbolAddress((void**)&pw1lo, g_w1lo);
    cudaGetSymbolAddress((void**)&pw2hi, g_w2hi);
    cudaGetSymbolAddress((void**)&pw2lo, g_w2lo);

    const int SM128 = 2 * 128 * (128 + 8) * 2 + 2 * 128 * 72 * 2;  // 106496
    const int SM64  = 2 * 128 * (64 + 8) * 2  + 2 * 64 * 72 * 2;   //  55296
    const int SMDEC = 2 * 128 * 72 * 2 + 6 * 64 * 72 * 2 + 512;    //  74240
    cudaFuncSetAttribute(mma_gemm_pre<128>, cudaFuncAttributeMaxDynamicSharedMemorySize, SM128);
    cudaFuncSetAttribute(mma_gemm_pre<64>,  cudaFuncAttributeMaxDynamicSharedMemorySize, SM64);
    cudaFuncSetAttribute(decode_kernel,     cudaFuncAttributeMaxDynamicSharedMemorySize, SMDEC);

    const int gbEdge = (N_EDGES + 255) / 256;

    // prep: zero degi + all operand splits (one kernel)
    prep_kernel<<<ZB + XB + W1B + W2B, 256>>>(x, W1, W2);
    // CSR build
    count_deg_kernel<<<gbEdge, 256>>>(dst);
    scan1_kernel    <<<NSCAN_BLOCKS, 256>>>();
    scan2_kernel    <<<1, 256>>>();
    scan3_kernel    <<<NSCAN_BLOCKS, 256>>>();
    fill_csr_kernel <<<gbEdge, 256>>>(src, dst);

    const int gbN  = (N_NODES + 127) / 128;   // 391
    const int gbEL = (N_EL    + 127) / 128;   // 782
    const int gbG  = (N_NODES + 7) / 8;       // 6250

    // conv layer 1: h1 = x@W1 ; gather (+bias+relu+split fused)
    mma_gemm_pre<128><<<gbN, 256, SM128>>>(pxhi, pxlo, pw1hi, pw1lo, ph1, N_NODES);
    gather_kernel<true><<<gbG, 256>>>(ph1, b1, nullptr);

    // conv layer 2: h2 = z1@W2 ; gather (b2 folded into decode)
    mma_gemm_pre<64><<<gbN, 256, SM64>>>(pz1hi, pz1lo, pw2hi, pw2lo, ph2, N_NODES);
    gather_kernel<false><<<gbG, 256>>>(ph2, nullptr, pz2);

    // fused decode
    decode_kernel<<<gbEL, 256, SMDEC>>>(eli, b2, P1, pb1, P2, pb2, P3, pb3, out);
}

// round 8
// speedup vs baseline: 1.8998x; 1.0534x over previous
#include <cuda_runtime.h>
#include <cuda_bf16.h>
#include <cstdint>

#define N_NODES 50000
#define N_EDGES 800000
#define N_EL    100000
#define NSCAN_BLOCKS ((N_NODES + 255) / 256)   // 196

// ---------------- scratch (device globals; no allocation allowed) ----------------
// INVARIANT: g_degi and g_scanstate are zero at the start of every run.
// (zero-initialized at module load; fill_csr_kernel restores both to zero each run)
__device__ int      g_degi     [N_NODES];
__device__ uint32_t g_scanstate[NSCAN_BLOCKS];
__device__ int      g_rowptr   [N_NODES + 1];
__device__ int      g_csr      [N_EDGES];
__device__ float g_dinv[N_NODES];
__device__ float g_h1  [N_NODES * 64];
__device__ float g_h2  [N_NODES * 64];
__device__ float g_z2  [N_NODES * 64];
// pre-split bf16 operand arrays
__device__ __nv_bfloat16 g_xhi [N_NODES * 128];
__device__ __nv_bfloat16 g_xlo [N_NODES * 128];
__device__ __nv_bfloat16 g_z1hi[N_NODES * 64];
__device__ __nv_bfloat16 g_z1lo[N_NODES * 64];
__device__ __nv_bfloat16 g_w1hi[128 * 64];
__device__ __nv_bfloat16 g_w1lo[128 * 64];
__device__ __nv_bfloat16 g_w2hi[64 * 64];
__device__ __nv_bfloat16 g_w2lo[64 * 64];

// ---------------- helpers ----------------
__device__ __forceinline__ uint32_t smem_u32(const void* p) {
    uint32_t a;
    asm("{ .reg .u64 t; cvta.to.shared.u64 t, %1; cvt.u32.u64 %0, t; }" : "=r"(a) : "l"(p));
    return a;
}
__device__ __forceinline__ uint32_t pack_bf16(float x, float y) {
    __nv_bfloat162 t = __floats2bfloat162_rn(x, y);
    return *(uint32_t*)&t;
}
__device__ __forceinline__ float bf_hi(float x) {
    return __bfloat162float(__float2bfloat16_rn(x));
}
__device__ __forceinline__ void cp16(uint32_t dst, const void* src, uint32_t sz) {
    asm volatile("cp.async.ca.shared.global [%0], [%1], 16, %2;"
                 :: "r"(dst), "l"(src), "r"(sz) : "memory");
}
__device__ __forceinline__ void cp_commit_wait() {
    asm volatile("cp.async.commit_group;");
    asm volatile("cp.async.wait_group 0;" ::: "memory");
}
__device__ __forceinline__ void ldsm_x4(uint32_t* r, uint32_t addr) {
    asm volatile("ldmatrix.sync.aligned.m8n8.x4.shared.b16 {%0,%1,%2,%3}, [%4];"
                 : "=r"(r[0]), "=r"(r[1]), "=r"(r[2]), "=r"(r[3]) : "r"(addr));
}
__device__ __forceinline__ void ldsm_x4_t(uint32_t* r, uint32_t addr) {
    asm volatile("ldmatrix.sync.aligned.m8n8.x4.trans.shared.b16 {%0,%1,%2,%3}, [%4];"
                 : "=r"(r[0]), "=r"(r[1]), "=r"(r[2]), "=r"(r[3]) : "r"(addr));
}
__device__ __forceinline__ void mma_bf16(float* d, const uint32_t* a, const uint32_t* b) {
    asm volatile("mma.sync.aligned.m16n8k16.row.col.f32.bf16.bf16.f32 "
                 "{%0,%1,%2,%3}, {%4,%5,%6,%7}, {%8,%9}, {%0,%1,%2,%3};"
                 : "+f"(d[0]), "+f"(d[1]), "+f"(d[2]), "+f"(d[3])
                 : "r"(a[0]), "r"(a[1]), "r"(a[2]), "r"(a[3]), "r"(b[0]), "r"(b[1]));
}
__device__ __forceinline__ void split_store(const float* __restrict__ in,
                                            __nv_bfloat16* __restrict__ hi,
                                            __nv_bfloat16* __restrict__ lo, int i) {
    float4 v = ((const float4*)in)[i];
    float hx = bf_hi(v.x), hy = bf_hi(v.y), hz = bf_hi(v.z), hw = bf_hi(v.w);
    ((uint2*)hi)[i] = make_uint2(pack_bf16(hx, hy), pack_bf16(hz, hw));
    ((uint2*)lo)[i] = make_uint2(pack_bf16(v.x - hx, v.y - hy), pack_bf16(v.z - hz, v.w - hw));
}
__device__ __forceinline__ int warp_incl_scan(int v, int lane) {
    #pragma unroll
    for (int o = 1; o < 32; o <<= 1) {
        int t = __shfl_up_sync(0xffffffffu, v, o);
        if (lane >= o) v += t;
    }
    return v;
}

// ---------------- K1: degree count + all operand splits (range-dispatched) ----------------
#define CB  ((N_EDGES + 255) / 256)          // 3125 blocks: count degrees
#define XB  ((N_NODES * 32 + 255) / 256)     // 6250 blocks: split x
#define W1B ((128 * 16 + 255) / 256)         // 8 blocks
#define W2B ((64 * 16 + 255) / 256)          // 4 blocks
__global__ void prep_count_kernel(const int* __restrict__ dst, const float* __restrict__ x,
                                  const float* __restrict__ W1, const float* __restrict__ W2) {
    int b = blockIdx.x;
    if (b < CB) {
        int e = b * 256 + threadIdx.x;
        if (e < N_EDGES) atomicAdd(&g_degi[dst[e]], 1);   // degi starts at 0 (invariant)
    } else if (b < CB + XB) {
        int i = (b - CB) * 256 + threadIdx.x;
        if (i < N_NODES * 32) split_store(x, g_xhi, g_xlo, i);
    } else if (b < CB + XB + W1B) {
        int i = (b - CB - XB) * 256 + threadIdx.x;
        if (i < 128 * 16) split_store(W1, g_w1hi, g_w1lo, i);
    } else {
        int i = (b - CB - XB - W1B) * 256 + threadIdx.x;
        if (i < 64 * 16) split_store(W2, g_w2hi, g_w2lo, i);
    }
}

// ---------------- K2: decoupled-lookback scan (+dinv) fused with gemm1 ----------------
// flags live in the TOP 2 bits of an UNSIGNED word (logical shift on read).
#define FLAG_AGG (1u << 30)
#define FLAG_PRE (2u << 30)
#define VAL_MASK 0x3FFFFFFFu

__device__ __forceinline__ void scan_block_body(int b) {
    __shared__ int wsum[8];
    __shared__ int s_base;
    int i = b * 256 + threadIdx.x;
    int lane = threadIdx.x & 31, w = threadIdx.x >> 5;

    int d = (i < N_NODES) ? g_degi[i] : 0;
    if (i < N_NODES) g_dinv[i] = rsqrtf((float)d + 1.0f);   // +1 = self-loop
    int s = warp_incl_scan(d, lane);
    if (lane == 31) wsum[w] = s;
    __syncthreads();
    if (w == 0) {
        int ws = (lane < 8) ? wsum[lane] : 0;
        ws = warp_incl_scan(ws, lane);
        if (lane < 8) wsum[lane] = ws;
    }
    __syncthreads();
    int base = (w > 0) ? wsum[w - 1] : 0;
    int incl = base + s;                 // inclusive within block
    uint32_t blocksum = (uint32_t)wsum[7];

    if (threadIdx.x == 0) {
        if (b == 0) {
            atomicExch(&g_scanstate[0], FLAG_PRE | blocksum);
            s_base = 0;
        } else {
            atomicExch(&g_scanstate[b], FLAG_AGG | blocksum);
        }
    }
    if (b > 0 && w == 0) {               // warp 0 lookback
        uint32_t exc = 0;
        int look = b - 1;
        while (true) {
            int idx = look - lane;
            uint32_t f = 0, val = 0;
            if (idx >= 0) {
                uint32_t v;
                do { v = atomicAdd(&g_scanstate[idx], 0u); } while ((v >> 30) == 0u);
                f = v >> 30;             // unsigned: 1=AGG, 2=PRE
                val = v & VAL_MASK;
            }
            unsigned pm = __ballot_sync(0xffffffffu, f == 2u);
            if (pm) {
                int cut = __ffs(pm) - 1;   // closest-to-look lane with a full prefix
                if (lane > cut) val = 0;
            }
            #pragma unroll
            for (int o = 16; o > 0; o >>= 1) val += __shfl_xor_sync(0xffffffffu, val, o);
            exc += val;
            if (pm) break;
            look -= 32;
        }
        if (lane == 0) {
            s_base = (int)exc;
            atomicExch(&g_scanstate[b], FLAG_PRE | (exc + blocksum));
        }
    }
    __syncthreads();
    if (i < N_NODES) g_rowptr[i] = s_base + incl - d;       // exclusive
    if (i == 0) g_rowptr[N_NODES] = N_EDGES;
}

__global__ __launch_bounds__(256)
void scan_gemm1_kernel(const __nv_bfloat16* __restrict__ Ahi, const __nv_bfloat16* __restrict__ Alo,
                       const __nv_bfloat16* __restrict__ Bhi, const __nv_bfloat16* __restrict__ Blo,
                       float* __restrict__ C, int M)
{
    if (blockIdx.x < NSCAN_BLOCKS) { scan_block_body(blockIdx.x); return; }

    constexpr int K = 128;
    constexpr int SA_H = K + 8;
    constexpr int SB_H = 72;
    constexpr int A_HI = 0;
    constexpr int A_LO = 128 * SA_H * 2;
    constexpr int B_HI = 2 * 128 * SA_H * 2;
    constexpr int B_LO = B_HI + K * SB_H * 2;

    extern __shared__ char smem[];
    const uint32_t sbase = smem_u32(smem);
    const int tid  = threadIdx.x;
    const int wid  = tid >> 5;
    const int lane = tid & 31;
    const int row0 = (blockIdx.x - NSCAN_BLOCKS) * 128;

    constexpr int ACH = K / 8;
    #pragma unroll
    for (int idx = tid; idx < 128 * ACH; idx += 256) {
        int r  = idx / ACH;
        int kc = (idx - r * ACH) * 8;
        int row = row0 + r;
        uint32_t sz = (row < M) ? 16u : 0u;
        size_t goff = (size_t)(row < M ? row : 0) * K + kc;
        uint32_t d = sbase + A_HI + (uint32_t)(r * SA_H + kc) * 2;
        cp16(d,                 &Ahi[goff], sz);
        cp16(d + (A_LO - A_HI), &Alo[goff], sz);
    }
    #pragma unroll
    for (int idx = tid; idx < K * 8; idx += 256) {
        int k = idx >> 3, nc = (idx & 7) * 8;
        uint32_t d = sbase + B_HI + (uint32_t)(k * SB_H + nc) * 2;
        cp16(d,                 &Bhi[k * 64 + nc], 16u);
        cp16(d + (B_LO - B_HI), &Blo[k * 64 + nc], 16u);
    }
    cp_commit_wait();
    __syncthreads();

    const int wm = (wid & 3) * 32;
    const int wn = (wid >> 2) * 32;
    const int lrow = lane & 15;
    const int lsel = (lane >> 4) * 8;

    float acc[2][4][4];
    #pragma unroll
    for (int mt = 0; mt < 2; mt++)
        #pragma unroll
        for (int nt = 0; nt < 4; nt++)
            #pragma unroll
            for (int i = 0; i < 4; i++) acc[mt][nt][i] = 0.f;

    #pragma unroll
    for (int k0 = 0; k0 < K; k0 += 16) {
        uint32_t a_hi[2][4], a_lo[2][4];
        #pragma unroll
        for (int mt = 0; mt < 2; mt++) {
            uint32_t off = (uint32_t)((wm + 16 * mt + lrow) * SA_H + k0 + lsel) * 2;
            ldsm_x4(a_hi[mt], sbase + A_HI + off);
            ldsm_x4(a_lo[mt], sbase + A_LO + off);
        }
        uint32_t b_hi[2][4], b_lo[2][4];
        #pragma unroll
        for (int h = 0; h < 2; h++) {
            uint32_t off = (uint32_t)((k0 + lrow) * SB_H + wn + 16 * h + lsel) * 2;
            ldsm_x4_t(b_hi[h], sbase + B_HI + off);
            ldsm_x4_t(b_lo[h], sbase + B_LO + off);
        }
        #pragma unroll
        for (int mt = 0; mt < 2; mt++)
            #pragma unroll
            for (int nt = 0; nt < 4; nt++) {
                const uint32_t* bh = &b_hi[nt >> 1][(nt & 1) * 2];
                const uint32_t* bl = &b_lo[nt >> 1][(nt & 1) * 2];
                mma_bf16(acc[mt][nt], a_hi[mt], bh);
                mma_bf16(acc[mt][nt], a_hi[mt], bl);
                mma_bf16(acc[mt][nt], a_lo[mt], bh);
            }
    }

    const int g  = lane >> 2;
    const int tg = lane & 3;
    #pragma unroll
    for (int mt = 0; mt < 2; mt++)
        #pragma unroll
        for (int rh = 0; rh < 2; rh++) {
            int row = row0 + wm + 16 * mt + g + 8 * rh;
            if (row >= M) continue;
            #pragma unroll
            for (int nt = 0; nt < 4; nt++) {
                int col = wn + 8 * nt + 2 * tg;
                *(float2*)&C[(size_t)row * 64 + col] =
                    make_float2(acc[mt][nt][2 * rh], acc[mt][nt][2 * rh + 1]);
            }
        }
}

// ---------------- K3: fill CSR (restores degi=0, scanstate=0 invariants) ----------------
__global__ void fill_csr_kernel(const int* __restrict__ src, const int* __restrict__ dst) {
    int e = blockIdx.x * 256 + threadIdx.x;
    if (blockIdx.x == 0 && threadIdx.x < NSCAN_BLOCKS) g_scanstate[threadIdx.x] = 0u;
    if (e >= N_EDGES) return;
    int d = dst[e];
    int old = atomicSub(&g_degi[d], 1);      // degi returns to 0 after this kernel
    g_csr[g_rowptr[d] + old - 1] = src[e];
}

// ---------------- pre-split mma GEMM (layer 2): C[M,64] = A[M,64] @ B[64,64] ----------------
template<int K>
__global__ __launch_bounds__(256)
void mma_gemm_pre(const __nv_bfloat16* __restrict__ Ahi, const __nv_bfloat16* __restrict__ Alo,
                  const __nv_bfloat16* __restrict__ Bhi, const __nv_bfloat16* __restrict__ Blo,
                  float* __restrict__ C, int M)
{
    constexpr int SA_H = K + 8;
    constexpr int SB_H = 72;
    constexpr int A_HI = 0;
    constexpr int A_LO = 128 * SA_H * 2;
    constexpr int B_HI = 2 * 128 * SA_H * 2;
    constexpr int B_LO = B_HI + K * SB_H * 2;

    extern __shared__ char smem[];
    const uint32_t sbase = smem_u32(smem);
    const int tid  = threadIdx.x;
    const int wid  = tid >> 5;
    const int lane = tid & 31;
    const int row0 = blockIdx.x * 128;

    constexpr int ACH = K / 8;
    #pragma unroll
    for (int idx = tid; idx < 128 * ACH; idx += 256) {
        int r  = idx / ACH;
        int kc = (idx - r * ACH) * 8;
        int row = row0 + r;
        uint32_t sz = (row < M) ? 16u : 0u;
        size_t goff = (size_t)(row < M ? row : 0) * K + kc;
        uint32_t d = sbase + A_HI + (uint32_t)(r * SA_H + kc) * 2;
        cp16(d,                 &Ahi[goff], sz);
        cp16(d + (A_LO - A_HI), &Alo[goff], sz);
    }
    #pragma unroll
    for (int idx = tid; idx < K * 8; idx += 256) {
        int k = idx >> 3, nc = (idx & 7) * 8;
        uint32_t d = sbase + B_HI + (uint32_t)(k * SB_H + nc) * 2;
        cp16(d,                 &Bhi[k * 64 + nc], 16u);
        cp16(d + (B_LO - B_HI), &Blo[k * 64 + nc], 16u);
    }
    cp_commit_wait();
    __syncthreads();

    const int wm = (wid & 3) * 32;
    const int wn = (wid >> 2) * 32;
    const int lrow = lane & 15;
    const int lsel = (lane >> 4) * 8;

    float acc[2][4][4];
    #pragma unroll
    for (int mt = 0; mt < 2; mt++)
        #pragma unroll
        for (int nt = 0; nt < 4; nt++)
            #pragma unroll
            for (int i = 0; i < 4; i++) acc[mt][nt][i] = 0.f;

    #pragma unroll
    for (int k0 = 0; k0 < K; k0 += 16) {
        uint32_t a_hi[2][4], a_lo[2][4];
        #pragma unroll
        for (int mt = 0; mt < 2; mt++) {
            uint32_t off = (uint32_t)((wm + 16 * mt + lrow) * SA_H + k0 + lsel) * 2;
            ldsm_x4(a_hi[mt], sbase + A_HI + off);
            ldsm_x4(a_lo[mt], sbase + A_LO + off);
        }
        uint32_t b_hi[2][4], b_lo[2][4];
        #pragma unroll
        for (int h = 0; h < 2; h++) {
            uint32_t off = (uint32_t)((k0 + lrow) * SB_H + wn + 16 * h + lsel) * 2;
            ldsm_x4_t(b_hi[h], sbase + B_HI + off);
            ldsm_x4_t(b_lo[h], sbase + B_LO + off);
        }
        #pragma unroll
        for (int mt = 0; mt < 2; mt++)
            #pragma unroll
            for (int nt = 0; nt < 4; nt++) {
                const uint32_t* bh = &b_hi[nt >> 1][(nt & 1) * 2];
                const uint32_t* bl = &b_lo[nt >> 1][(nt & 1) * 2];
                mma_bf16(acc[mt][nt], a_hi[mt], bh);
                mma_bf16(acc[mt][nt], a_hi[mt], bl);
                mma_bf16(acc[mt][nt], a_lo[mt], bh);
            }
    }

    const int g  = lane >> 2;
    const int tg = lane & 3;
    #pragma unroll
    for (int mt = 0; mt < 2; mt++)
        #pragma unroll
        for (int rh = 0; rh < 2; rh++) {
            int row = row0 + wm + 16 * mt + g + 8 * rh;
            if (row >= M) continue;
            #pragma unroll
            for (int nt = 0; nt < 4; nt++) {
                int col = wn + 8 * nt + 2 * tg;
                *(float2*)&C[(size_t)row * 64 + col] =
                    make_float2(acc[mt][nt][2 * rh], acc[mt][nt][2 * rh + 1]);
            }
        }
}

// ---------------- CSR gather, 4-wide unrolled ----------------
template<bool LAYER1>
__global__ __launch_bounds__(256)
void gather_kernel(const float* __restrict__ h, const float* __restrict__ bias,
                   float* __restrict__ zout)
{
    int node = blockIdx.x * 8 + (threadIdx.x >> 5);   // warp per node
    int lane = threadIdx.x & 31;
    if (node >= N_NODES) return;

    float dd = g_dinv[node];
    float2 a0 = *(const float2*)&h[(size_t)node * 64 + lane * 2];   // self-loop
    a0.x *= dd * dd; a0.y *= dd * dd;
    float2 a1 = make_float2(0.f, 0.f);
    float2 a2 = make_float2(0.f, 0.f);
    float2 a3 = make_float2(0.f, 0.f);

    int e   = __ldg(&g_rowptr[node]);
    int end = __ldg(&g_rowptr[node + 1]);
    for (; e + 3 < end; e += 4) {
        int s0 = __ldg(&g_csr[e]);
        int s1 = __ldg(&g_csr[e + 1]);
        int s2 = __ldg(&g_csr[e + 2]);
        int s3 = __ldg(&g_csr[e + 3]);
        float w0 = __ldg(&g_dinv[s0]) * dd;
        float w1 = __ldg(&g_dinv[s1]) * dd;
        float w2 = __ldg(&g_dinv[s2]) * dd;
        float w3 = __ldg(&g_dinv[s3]) * dd;
        float2 v0 = *(const float2*)&h[(size_t)s0 * 64 + lane * 2];
        float2 v1 = *(const float2*)&h[(size_t)s1 * 64 + lane * 2];
        float2 v2 = *(const float2*)&h[(size_t)s2 * 64 + lane * 2];
        float2 v3 = *(const float2*)&h[(size_t)s3 * 64 + lane * 2];
        a0.x += v0.x * w0; a0.y += v0.y * w0;
        a1.x += v1.x * w1; a1.y += v1.y * w1;
        a2.x += v2.x * w2; a2.y += v2.y * w2;
        a3.x += v3.x * w3; a3.y += v3.y * w3;
    }
    for (; e < end; e++) {
        int s = __ldg(&g_csr[e]);
        float w = __ldg(&g_dinv[s]) * dd;
        float2 v = *(const float2*)&h[(size_t)s * 64 + lane * 2];
        a0.x += v.x * w; a0.y += v.y * w;
    }
    float2 acc = make_float2((a0.x + a1.x) + (a2.x + a3.x),
                             (a0.y + a1.y) + (a2.y + a3.y));

    if (LAYER1) {
        float2 b = *(const float2*)&bias[lane * 2];
        float vx = fmaxf(acc.x + b.x, 0.f);
        float vy = fmaxf(acc.y + b.y, 0.f);
        float hx = bf_hi(vx), hy = bf_hi(vy);
        ((uint32_t*)g_z1hi)[node * 32 + lane] = pack_bf16(hx, hy);
        ((uint32_t*)g_z1lo)[node * 32 + lane] = pack_bf16(vx - hx, vy - hy);
    } else {
        *(float2*)&zout[(size_t)node * 64 + lane * 2] = acc;
    }
}

// ---------------- fused decode: ef -> P1+relu -> P2+relu -> P3 dot ----------------
__global__ __launch_bounds__(256)
void decode_kernel(const int* __restrict__ eli, const float* __restrict__ b2,
                   const float* __restrict__ P1, const float* __restrict__ pb1,
                   const float* __restrict__ P2, const float* __restrict__ pb2,
                   const float* __restrict__ P3, const float* __restrict__ pb3,
                   float* __restrict__ out)
{
    constexpr int SA_H = 72, SB_H = 72;
    constexpr int EF_HI = 0;
    constexpr int EF_LO = 128 * SA_H * 2;
    constexpr int P1_HI = 2 * 128 * SA_H * 2;
    constexpr int P1_LO = P1_HI + 64 * SB_H * 2;
    constexpr int P2_HI = P1_LO + 64 * SB_H * 2;
    constexpr int P2_LO = P2_HI + 64 * SB_H * 2;
    constexpr int S_OUT = P2_LO + 64 * SB_H * 2;

    extern __shared__ char smem[];
    const uint32_t sbase = smem_u32(smem);
    const int tid  = threadIdx.x;
    const int wid  = tid >> 5;
    const int lane = tid & 31;
    const int row0 = blockIdx.x * 128;

    if (tid < 128) *(float*)(smem + S_OUT + tid * 4) = 0.f;

    #pragma unroll
    for (int idx = tid; idx < 128 * 16; idx += 256) {
        int pl = idx >> 4, c4 = (idx & 15) << 2;
        int p = row0 + pl;
        float4 r = make_float4(0.f, 0.f, 0.f, 0.f);
        if (p < N_EL) {
            int a = __ldg(&eli[p]);
            int b = __ldg(&eli[N_EL + p]);
            float4 bb = *(const float4*)&b2[c4];
            float4 za = *(const float4*)&g_z2[a * 64 + c4];
            float4 zb = *(const float4*)&g_z2[b * 64 + c4];
            r.x = (za.x + bb.x) * (zb.x + bb.x);
            r.y = (za.y + bb.y) * (zb.y + bb.y);
            r.z = (za.z + bb.z) * (zb.z + bb.z);
            r.w = (za.w + bb.w) * (zb.w + bb.w);
        }
        float hx = bf_hi(r.x), hy = bf_hi(r.y), hz = bf_hi(r.z), hw = bf_hi(r.w);
        uint32_t off = (uint32_t)(pl * SA_H + c4) * 2;
        *(uint2*)(smem + EF_HI + off) = make_uint2(pack_bf16(hx, hy), pack_bf16(hz, hw));
        *(uint2*)(smem + EF_LO + off) = make_uint2(pack_bf16(r.x - hx, r.y - hy),
                                                   pack_bf16(r.z - hz, r.w - hw));
    }
    #pragma unroll
    for (int idx = tid; idx < 64 * 16; idx += 256) {
        int k = idx >> 4, nc = (idx & 15) << 2;
        uint32_t off = (uint32_t)(k * SB_H + nc) * 2;
        float4 v = *(const float4*)&P1[k * 64 + nc];
        float hx = bf_hi(v.x), hy = bf_hi(v.y), hz = bf_hi(v.z), hw = bf_hi(v.w);
        *(uint2*)(smem + P1_HI + off) = make_uint2(pack_bf16(hx, hy), pack_bf16(hz, hw));
        *(uint2*)(smem + P1_LO + off) = make_uint2(pack_bf16(v.x - hx, v.y - hy),
                                                   pack_bf16(v.z - hz, v.w - hw));
        float4 u = *(const float4*)&P2[k * 64 + nc];
        float ux = bf_hi(u.x), uy = bf_hi(u.y), uz = bf_hi(u.z), uw = bf_hi(u.w);
        *(uint2*)(smem + P2_HI + off) = make_uint2(pack_bf16(ux, uy), pack_bf16(uz, uw));
        *(uint2*)(smem + P2_LO + off) = make_uint2(pack_bf16(u.x - ux, u.y - uy),
                                                   pack_bf16(u.z - uz, u.w - uw));
    }
    __syncthreads();

    const int wm = (wid & 3) * 32;
    const int wn = (wid >> 2) * 32;
    const int lrow = lane & 15;
    const int lsel = (lane >> 4) * 8;
    const int g  = lane >> 2;
    const int tg = lane & 3;

    float acc[2][4][4];
    #pragma unroll
    for (int mt = 0; mt < 2; mt++)
        #pragma unroll
        for (int nt = 0; nt < 4; nt++)
            #pragma unroll
            for (int i = 0; i < 4; i++) acc[mt][nt][i] = 0.f;

    #pragma unroll
    for (int k0 = 0; k0 < 64; k0 += 16) {
        uint32_t a_hi[2][4], a_lo[2][4];
        #pragma unroll
        for (int mt = 0; mt < 2; mt++) {
            uint32_t off = (uint32_t)((wm + 16 * mt + lrow) * SA_H + k0 + lsel) * 2;
            ldsm_x4(a_hi[mt], sbase + EF_HI + off);
            ldsm_x4(a_lo[mt], sbase + EF_LO + off);
        }
        uint32_t b_hi[2][4], b_lo[2][4];
        #pragma unroll
        for (int h = 0; h < 2; h++) {
            uint32_t off = (uint32_t)((k0 + lrow) * SB_H + wn + 16 * h + lsel) * 2;
            ldsm_x4_t(b_hi[h], sbase + P1_HI + off);
            ldsm_x4_t(b_lo[h], sbase + P1_LO + off);
        }
        #pragma unroll
        for (int mt = 0; mt < 2; mt++)
            #pragma unroll
            for (int nt = 0; nt < 4; nt++) {
                const uint32_t* bh = &b_hi[nt >> 1][(nt & 1) * 2];
                const uint32_t* bl = &b_lo[nt >> 1][(nt & 1) * 2];
                mma_bf16(acc[mt][nt], a_hi[mt], bh);
                mma_bf16(acc[mt][nt], a_hi[mt], bl);
                mma_bf16(acc[mt][nt], a_lo[mt], bh);
            }
    }
    __syncthreads();

    #pragma unroll
    for (int mt = 0; mt < 2; mt++)
        #pragma unroll
        for (int rh = 0; rh < 2; rh++) {
            int rl = wm + 16 * mt + g + 8 * rh;
            #pragma unroll
            for (int nt = 0; nt < 4; nt++) {
                int col = wn + 8 * nt + 2 * tg;
                float vx = fmaxf(acc[mt][nt][2 * rh]     + __ldg(&pb1[col]),     0.f);
                float vy = fmaxf(acc[mt][nt][2 * rh + 1] + __ldg(&pb1[col + 1]), 0.f);
                float hx = bf_hi(vx), hy = bf_hi(vy);
                uint32_t off = (uint32_t)(rl * SA_H + col) * 2;
                *(uint32_t*)(smem + EF_HI + off) = pack_bf16(hx, hy);
                *(uint32_t*)(smem + EF_LO + off) = pack_bf16(vx - hx, vy - hy);
            }
        }
    __syncthreads();

    #pragma unroll
    for (int mt = 0; mt < 2; mt++)
        #pragma unroll
        for (int nt = 0; nt < 4; nt++)
            #pragma unroll
            for (int i = 0; i < 4; i++) acc[mt][nt][i] = 0.f;

    #pragma unroll
    for (int k0 = 0; k0 < 64; k0 += 16) {
        uint32_t a_hi[2][4], a_lo[2][4];
        #pragma unroll
        for (int mt = 0; mt < 2; mt++) {
            uint32_t off = (uint32_t)((wm + 16 * mt + lrow) * SA_H + k0 + lsel) * 2;
            ldsm_x4(a_hi[mt], sbase + EF_HI + off);
            ldsm_x4(a_lo[mt], sbase + EF_LO + off);
        }
        uint32_t b_hi[2][4], b_lo[2][4];
        #pragma unroll
        for (int h = 0; h < 2; h++) {
            uint32_t off = (uint32_t)((k0 + lrow) * SB_H + wn + 16 * h + lsel) * 2;
            ldsm_x4_t(b_hi[h], sbase + P2_HI + off);
            ldsm_x4_t(b_lo[h], sbase + P2_LO + off);
        }
        #pragma unroll
        for (int mt = 0; mt < 2; mt++)
            #pragma unroll
            for (int nt = 0; nt < 4; nt++) {
                const uint32_t* bh = &b_hi[nt >> 1][(nt & 1) * 2];
                const uint32_t* bl = &b_lo[nt >> 1][(nt & 1) * 2];
                mma_bf16(acc[mt][nt], a_hi[mt], bh);
                mma_bf16(acc[mt][nt], a_hi[mt], bl);
                mma_bf16(acc[mt][nt], a_lo[mt], bh);
            }
    }

    #pragma unroll
    for (int mt = 0; mt < 2; mt++)
        #pragma unroll
        for (int rh = 0; rh < 2; rh++) {
            float s = 0.f;
            #pragma unroll
            for (int nt = 0; nt < 4; nt++) {
                int col = wn + 8 * nt + 2 * tg;
                float vx = fmaxf(acc[mt][nt][2 * rh]     + __ldg(&pb2[col]),     0.f);
                float vy = fmaxf(acc[mt][nt][2 * rh + 1] + __ldg(&pb2[col + 1]), 0.f);
                s += vx * __ldg(&P3[col]) + vy * __ldg(&P3[col + 1]);
            }
            s += __shfl_xor_sync(0xffffffffu, s, 1);
            s += __shfl_xor_sync(0xffffffffu, s, 2);
            if (tg == 0) {
                int rl = wm + 16 * mt + g + 8 * rh;
                atomicAdd((float*)(smem + S_OUT) + rl, s);
            }
        }
    __syncthreads();
    if (tid < 128) {
        int p = row0 + tid;
        if (p < N_EL) out[p] = *(float*)(smem + S_OUT + tid * 4) + __ldg(&pb3[0]);
    }
}

// ---------------- launcher ----------------
extern "C" void kernel_launch(void* const* d_in, const int* in_sizes, int n_in,
                              void* d_out, int out_size)
{
    const float* x   = (const float*)d_in[0];
    const int*   ei  = (const int*)  d_in[1];
    const int*   eli = (const int*)  d_in[2];
    const float* W1  = (const float*)d_in[3];
    const float* b1  = (const float*)d_in[4];
    const float* W2  = (const float*)d_in[5];
    const float* b2  = (const float*)d_in[6];
    const float* P1  = (const float*)d_in[7];
    const float* pb1 = (const float*)d_in[8];
    const float* P2  = (const float*)d_in[9];
    const float* pb2 = (const float*)d_in[10];
    const float* P3  = (const float*)d_in[11];
    const float* pb3 = (const float*)d_in[12];
    float* out = (float*)d_out;

    const int* src = ei;
    const int* dst = ei + N_EDGES;

    float *ph1, *ph2, *pz2;
    cudaGetSymbolAddress((void**)&ph1, g_h1);
    cudaGetSymbolAddress((void**)&ph2, g_h2);
    cudaGetSymbolAddress((void**)&pz2, g_z2);
    __nv_bfloat16 *pxhi, *pxlo, *pz1hi, *pz1lo, *pw1hi, *pw1lo, *pw2hi, *pw2lo;
    cudaGetSymbolAddress((void**)&pxhi,  g_xhi);
    cudaGetSymbolAddress((void**)&pxlo,  g_xlo);
    cudaGetSymbolAddress((void**)&pz1hi, g_z1hi);
    cudaGetSymbolAddress((void**)&pz1lo, g_z1lo);
    cudaGetSymbolAddress((void**)&pw1hi, g_w1hi);
    cudaGetSymbolAddress((void**)&pw1lo, g_w1lo);
    cudaGetSymbolAddress((void**)&pw2hi, g_w2hi);
    cudaGetSymbolAddress((void**)&pw2lo, g_w2lo);

    const int SM128 = 2 * 128 * (128 + 8) * 2 + 2 * 128 * 72 * 2;  // 106496
    const int SM64  = 2 * 128 * (64 + 8) * 2  + 2 * 64 * 72 * 2;   //  55296
    const int SMDEC = 2 * 128 * 72 * 2 + 6 * 64 * 72 * 2 + 512;    //  74240
    cudaFuncSetAttribute(scan_gemm1_kernel, cudaFuncAttributeMaxDynamicSharedMemorySize, SM128);
    cudaFuncSetAttribute(mma_gemm_pre<64>,  cudaFuncAttributeMaxDynamicSharedMemorySize, SM64);
    cudaFuncSetAttribute(decode_kernel,     cudaFuncAttributeMaxDynamicSharedMemorySize, SMDEC);

    const int gbN  = (N_NODES + 127) / 128;   // 391
    const int gbEL = (N_EL    + 127) / 128;   // 782
    const int gbG  = (N_NODES + 7) / 8;       // 6250

    // K1: degree count + operand splits (degi starts at 0 by invariant)
    prep_count_kernel<<<CB + XB + W1B + W2B, 256>>>(dst, x, W1, W2);
    // K2: lookback scan (+dinv) fused with gemm1 (scan blocks first => wave-1 resident)
    scan_gemm1_kernel<<<NSCAN_BLOCKS + gbN, 256, SM128>>>(pxhi, pxlo, pw1hi, pw1lo, ph1, N_NODES);
    // K3: CSR fill (restores degi=0, scanstate=0)
    fill_csr_kernel<<<CB, 256>>>(src, dst);
    // gather layer 1 (+bias+relu+split fused)
    gather_kernel<true><<<gbG, 256>>>(ph1, b1, nullptr);
    // conv layer 2
    mma_gemm_pre<64><<<gbN, 256, SM64>>>(pz1hi, pz1lo, pw2hi, pw2lo, ph2, N_NODES);
    gather_kernel<false><<<gbG, 256>>>(ph2, nullptr, pz2);
    // fused decode
    decode_kernel<<<gbEL, 256, SMDEC>>>(eli, b2, P1, pb1, P2, pb2, P3, pb3, out);
}

// round 10
// speedup vs baseline: 1.9248x; 1.0132x over previous
#include <cuda_runtime.h>
#include <cuda_bf16.h>
#include <cstdint>

#define N_NODES 50000
#define N_EDGES 800000
#define N_EL    100000
#define NSCAN_BLOCKS ((N_NODES + 255) / 256)   // 196

// ---------------- scratch (device globals; no allocation allowed) ----------------
// INVARIANT: g_degi, g_scanstate, g_scandone are zero at the start of every run.
// (zero-initialized at module load; fill_csr_kernel restores them each run)
__device__ int      g_degi     [N_NODES];
__device__ uint32_t g_scanstate[NSCAN_BLOCKS];
__device__ int      g_scandone;
__device__ int      g_rowptr   [N_NODES + 1];
__device__ int      g_csr      [N_EDGES];      // BYTE offsets: src*256
__device__ float g_dinv[N_NODES];
__device__ float g_h1  [N_NODES * 64];         // scaled: h1*dinv[row]
__device__ float g_h2  [N_NODES * 64];         // scaled: h2*dinv[row]
__device__ float g_z2  [N_NODES * 64];
// pre-split bf16 operand arrays
__device__ __nv_bfloat16 g_xhi [N_NODES * 128];
__device__ __nv_bfloat16 g_xlo [N_NODES * 128];
__device__ __nv_bfloat16 g_z1hi[N_NODES * 64];
__device__ __nv_bfloat16 g_z1lo[N_NODES * 64];
__device__ __nv_bfloat16 g_w1hi[128 * 64];
__device__ __nv_bfloat16 g_w1lo[128 * 64];
__device__ __nv_bfloat16 g_w2hi[64 * 64];
__device__ __nv_bfloat16 g_w2lo[64 * 64];

// ---------------- helpers ----------------
__device__ __forceinline__ uint32_t smem_u32(const void* p) {
    uint32_t a;
    asm("{ .reg .u64 t; cvta.to.shared.u64 t, %1; cvt.u32.u64 %0, t; }" : "=r"(a) : "l"(p));
    return a;
}
__device__ __forceinline__ uint32_t pack_bf16(float x, float y) {
    __nv_bfloat162 t = __floats2bfloat162_rn(x, y);
    return *(uint32_t*)&t;
}
__device__ __forceinline__ float bf_hi(float x) {
    return __bfloat162float(__float2bfloat16_rn(x));
}
__device__ __forceinline__ void cp16(uint32_t dst, const void* src, uint32_t sz) {
    asm volatile("cp.async.ca.shared.global [%0], [%1], 16, %2;"
                 :: "r"(dst), "l"(src), "r"(sz) : "memory");
}
__device__ __forceinline__ void cp_commit_wait() {
    asm volatile("cp.async.commit_group;");
    asm volatile("cp.async.wait_group 0;" ::: "memory");
}
__device__ __forceinline__ void ldsm_x4(uint32_t* r, uint32_t addr) {
    asm volatile("ldmatrix.sync.aligned.m8n8.x4.shared.b16 {%0,%1,%2,%3}, [%4];"
                 : "=r"(r[0]), "=r"(r[1]), "=r"(r[2]), "=r"(r[3]) : "r"(addr));
}
__device__ __forceinline__ void ldsm_x4_t(uint32_t* r, uint32_t addr) {
    asm volatile("ldmatrix.sync.aligned.m8n8.x4.trans.shared.b16 {%0,%1,%2,%3}, [%4];"
                 : "=r"(r[0]), "=r"(r[1]), "=r"(r[2]), "=r"(r[3]) : "r"(addr));
}
__device__ __forceinline__ void mma_bf16(float* d, const uint32_t* a, const uint32_t* b) {
    asm volatile("mma.sync.aligned.m16n8k16.row.col.f32.bf16.bf16.f32 "
                 "{%0,%1,%2,%3}, {%4,%5,%6,%7}, {%8,%9}, {%0,%1,%2,%3};"
                 : "+f"(d[0]), "+f"(d[1]), "+f"(d[2]), "+f"(d[3])
                 : "r"(a[0]), "r"(a[1]), "r"(a[2]), "r"(a[3]), "r"(b[0]), "r"(b[1]));
}
__device__ __forceinline__ void split_store(const float* __restrict__ in,
                                            __nv_bfloat16* __restrict__ hi,
                                            __nv_bfloat16* __restrict__ lo, int i) {
    float4 v = ((const float4*)in)[i];
    float hx = bf_hi(v.x), hy = bf_hi(v.y), hz = bf_hi(v.z), hw = bf_hi(v.w);
    ((uint2*)hi)[i] = make_uint2(pack_bf16(hx, hy), pack_bf16(hz, hw));
    ((uint2*)lo)[i] = make_uint2(pack_bf16(v.x - hx, v.y - hy), pack_bf16(v.z - hz, v.w - hw));
}
__device__ __forceinline__ int warp_incl_scan(int v, int lane) {
    #pragma unroll
    for (int o = 1; o < 32; o <<= 1) {
        int t = __shfl_up_sync(0xffffffffu, v, o);
        if (lane >= o) v += t;
    }
    return v;
}

// ---------------- K1: degree count + all operand splits (range-dispatched) ----------------
#define CB  ((N_EDGES + 255) / 256)          // 3125 blocks: count degrees
#define XB  ((N_NODES * 32 + 255) / 256)     // 6250 blocks: split x
#define W1B ((128 * 16 + 255) / 256)         // 8 blocks
#define W2B ((64 * 16 + 255) / 256)          // 4 blocks
__global__ void prep_count_kernel(const int* __restrict__ dst, const float* __restrict__ x,
                                  const float* __restrict__ W1, const float* __restrict__ W2) {
    int b = blockIdx.x;
    if (b < CB) {
        int e = b * 256 + threadIdx.x;
        if (e < N_EDGES) atomicAdd(&g_degi[dst[e]], 1);   // degi starts at 0 (invariant)
    } else if (b < CB + XB) {
        int i = (b - CB) * 256 + threadIdx.x;
        if (i < N_NODES * 32) split_store(x, g_xhi, g_xlo, i);
    } else if (b < CB + XB + W1B) {
        int i = (b - CB - XB) * 256 + threadIdx.x;
        if (i < 128 * 16) split_store(W1, g_w1hi, g_w1lo, i);
    } else {
        int i = (b - CB - XB - W1B) * 256 + threadIdx.x;
        if (i < 64 * 16) split_store(W2, g_w2hi, g_w2lo, i);
    }
}

// ---------------- K2: decoupled-lookback scan (+dinv) fused with gemm1 ----------------
#define FLAG_AGG (1u << 30)
#define FLAG_PRE (2u << 30)
#define VAL_MASK 0x3FFFFFFFu

__device__ __forceinline__ void scan_block_body(int b) {
    __shared__ int wsum[8];
    __shared__ int s_base;
    int i = b * 256 + threadIdx.x;
    int lane = threadIdx.x & 31, w = threadIdx.x >> 5;

    int d = (i < N_NODES) ? g_degi[i] : 0;
    if (i < N_NODES) g_dinv[i] = rsqrtf((float)d + 1.0f);   // +1 = self-loop
    int s = warp_incl_scan(d, lane);
    if (lane == 31) wsum[w] = s;
    __syncthreads();
    if (w == 0) {
        int ws = (lane < 8) ? wsum[lane] : 0;
        ws = warp_incl_scan(ws, lane);
        if (lane < 8) wsum[lane] = ws;
    }
    __syncthreads();
    int base = (w > 0) ? wsum[w - 1] : 0;
    int incl = base + s;                 // inclusive within block
    uint32_t blocksum = (uint32_t)wsum[7];

    if (threadIdx.x == 0) {
        if (b == 0) {
            atomicExch(&g_scanstate[0], FLAG_PRE | blocksum);
            s_base = 0;
        } else {
            atomicExch(&g_scanstate[b], FLAG_AGG | blocksum);
        }
    }
    if (b > 0 && w == 0) {               // warp 0 lookback
        uint32_t exc = 0;
        int look = b - 1;
        while (true) {
            int idx = look - lane;
            uint32_t f = 0, val = 0;
            if (idx >= 0) {
                uint32_t v;
                do { v = atomicAdd(&g_scanstate[idx], 0u); } while ((v >> 30) == 0u);
                f = v >> 30;
                val = v & VAL_MASK;
            }
            unsigned pm = __ballot_sync(0xffffffffu, f == 2u);
            if (pm) {
                int cut = __ffs(pm) - 1;
                if (lane > cut) val = 0;
            }
            #pragma unroll
            for (int o = 16; o > 0; o >>= 1) val += __shfl_xor_sync(0xffffffffu, val, o);
            exc += val;
            if (pm) break;
            look -= 32;
        }
        if (lane == 0) {
            s_base = (int)exc;
            atomicExch(&g_scanstate[b], FLAG_PRE | (exc + blocksum));
        }
    }
    __syncthreads();
    if (i < N_NODES) g_rowptr[i] = s_base + incl - d;       // exclusive
    if (i == 0) g_rowptr[N_NODES] = N_EDGES;
    // signal dinv/rowptr complete (gemm epilogues wait on this)
    __syncthreads();
    if (threadIdx.x == 0) {
        __threadfence();
        atomicAdd(&g_scandone, 1);
    }
}

__global__ __launch_bounds__(256)
void scan_gemm1_kernel(const __nv_bfloat16* __restrict__ Ahi, const __nv_bfloat16* __restrict__ Alo,
                       const __nv_bfloat16* __restrict__ Bhi, const __nv_bfloat16* __restrict__ Blo,
                       float* __restrict__ C, int M)
{
    if (blockIdx.x < NSCAN_BLOCKS) { scan_block_body(blockIdx.x); return; }

    constexpr int K = 128;
    constexpr int SA_H = K + 8;
    constexpr int SB_H = 72;
    constexpr int A_HI = 0;
    constexpr int A_LO = 128 * SA_H * 2;
    constexpr int B_HI = 2 * 128 * SA_H * 2;
    constexpr int B_LO = B_HI + K * SB_H * 2;

    extern __shared__ char smem[];
    const uint32_t sbase = smem_u32(smem);
    const int tid  = threadIdx.x;
    const int wid  = tid >> 5;
    const int lane = tid & 31;
    const int row0 = (blockIdx.x - NSCAN_BLOCKS) * 128;

    constexpr int ACH = K / 8;
    #pragma unroll
    for (int idx = tid; idx < 128 * ACH; idx += 256) {
        int r  = idx / ACH;
        int kc = (idx - r * ACH) * 8;
        int row = row0 + r;
        uint32_t sz = (row < M) ? 16u : 0u;
        size_t goff = (size_t)(row < M ? row : 0) * K + kc;
        uint32_t d = sbase + A_HI + (uint32_t)(r * SA_H + kc) * 2;
        cp16(d,                 &Ahi[goff], sz);
        cp16(d + (A_LO - A_HI), &Alo[goff], sz);
    }
    #pragma unroll
    for (int idx = tid; idx < K * 8; idx += 256) {
        int k = idx >> 3, nc = (idx & 7) * 8;
        uint32_t d = sbase + B_HI + (uint32_t)(k * SB_H + nc) * 2;
        cp16(d,                 &Bhi[k * 64 + nc], 16u);
        cp16(d + (B_LO - B_HI), &Blo[k * 64 + nc], 16u);
    }
    cp_commit_wait();
    __syncthreads();

    const int wm = (wid & 3) * 32;
    const int wn = (wid >> 2) * 32;
    const int lrow = lane & 15;
    const int lsel = (lane >> 4) * 8;

    float acc[2][4][4];
    #pragma unroll
    for (int mt = 0; mt < 2; mt++)
        #pragma unroll
        for (int nt = 0; nt < 4; nt++)
            #pragma unroll
            for (int i = 0; i < 4; i++) acc[mt][nt][i] = 0.f;

    #pragma unroll
    for (int k0 = 0; k0 < K; k0 += 16) {
        uint32_t a_hi[2][4], a_lo[2][4];
        #pragma unroll
        for (int mt = 0; mt < 2; mt++) {
            uint32_t off = (uint32_t)((wm + 16 * mt + lrow) * SA_H + k0 + lsel) * 2;
            ldsm_x4(a_hi[mt], sbase + A_HI + off);
            ldsm_x4(a_lo[mt], sbase + A_LO + off);
        }
        uint32_t b_hi[2][4], b_lo[2][4];
        #pragma unroll
        for (int h = 0; h < 2; h++) {
            uint32_t off = (uint32_t)((k0 + lrow) * SB_H + wn + 16 * h + lsel) * 2;
            ldsm_x4_t(b_hi[h], sbase + B_HI + off);
            ldsm_x4_t(b_lo[h], sbase + B_LO + off);
        }
        #pragma unroll
        for (int mt = 0; mt < 2; mt++)
            #pragma unroll
            for (int nt = 0; nt < 4; nt++) {
                const uint32_t* bh = &b_hi[nt >> 1][(nt & 1) * 2];
                const uint32_t* bl = &b_lo[nt >> 1][(nt & 1) * 2];
                mma_bf16(acc[mt][nt], a_hi[mt], bh);
                mma_bf16(acc[mt][nt], a_hi[mt], bl);
                mma_bf16(acc[mt][nt], a_lo[mt], bh);
            }
    }

    // wait for scan blocks (dinv ready); one thread spins, all sync after
    __shared__ int s_ready;
    if (tid == 0) {
        while (atomicAdd(&g_scandone, 0) < NSCAN_BLOCKS) {}
        __threadfence();
        s_ready = 1;
    }
    __syncthreads();

    const int g  = lane >> 2;
    const int tg = lane & 3;
    #pragma unroll
    for (int mt = 0; mt < 2; mt++)
        #pragma unroll
        for (int rh = 0; rh < 2; rh++) {
            int row = row0 + wm + 16 * mt + g + 8 * rh;
            if (row >= M) continue;
            float di = g_dinv[row];
            #pragma unroll
            for (int nt = 0; nt < 4; nt++) {
                int col = wn + 8 * nt + 2 * tg;
                *(float2*)&C[(size_t)row * 64 + col] =
                    make_float2(acc[mt][nt][2 * rh] * di, acc[mt][nt][2 * rh + 1] * di);
            }
        }
}

// ---------------- K3: fill CSR (byte offsets; restores invariants) ----------------
__global__ void fill_csr_kernel(const int* __restrict__ src, const int* __restrict__ dst) {
    int e = blockIdx.x * 256 + threadIdx.x;
    if (blockIdx.x == 0) {
        if (threadIdx.x < NSCAN_BLOCKS) g_scanstate[threadIdx.x] = 0u;
        if (threadIdx.x == 0) g_scandone = 0;
    }
    if (e >= N_EDGES) return;
    int d = dst[e];
    int old = atomicSub(&g_degi[d], 1);      // degi returns to 0 after this kernel
    g_csr[g_rowptr[d] + old - 1] = src[e] << 8;   // byte offset: src*256
}

// ---------------- pre-split mma GEMM (layer 2), epilogue scaled by dinv ----------------
template<int K>
__global__ __launch_bounds__(256)
void mma_gemm_pre(const __nv_bfloat16* __restrict__ Ahi, const __nv_bfloat16* __restrict__ Alo,
                  const __nv_bfloat16* __restrict__ Bhi, const __nv_bfloat16* __restrict__ Blo,
                  float* __restrict__ C, int M)
{
    constexpr int SA_H = K + 8;
    constexpr int SB_H = 72;
    constexpr int A_HI = 0;
    constexpr int A_LO = 128 * SA_H * 2;
    constexpr int B_HI = 2 * 128 * SA_H * 2;
    constexpr int B_LO = B_HI + K * SB_H * 2;

    extern __shared__ char smem[];
    const uint32_t sbase = smem_u32(smem);
    const int tid  = threadIdx.x;
    const int wid  = tid >> 5;
    const int lane = tid & 31;
    const int row0 = blockIdx.x * 128;

    constexpr int ACH = K / 8;
    #pragma unroll
    for (int idx = tid; idx < 128 * ACH; idx += 256) {
        int r  = idx / ACH;
        int kc = (idx - r * ACH) * 8;
        int row = row0 + r;
        uint32_t sz = (row < M) ? 16u : 0u;
        size_t goff = (size_t)(row < M ? row : 0) * K + kc;
        uint32_t d = sbase + A_HI + (uint32_t)(r * SA_H + kc) * 2;
        cp16(d,                 &Ahi[goff], sz);
        cp16(d + (A_LO - A_HI), &Alo[goff], sz);
    }
    #pragma unroll
    for (int idx = tid; idx < K * 8; idx += 256) {
        int k = idx >> 3, nc = (idx & 7) * 8;
        uint32_t d = sbase + B_HI + (uint32_t)(k * SB_H + nc) * 2;
        cp16(d,                 &Bhi[k * 64 + nc], 16u);
        cp16(d + (B_LO - B_HI), &Blo[k * 64 + nc], 16u);
    }
    cp_commit_wait();
    __syncthreads();

    const int wm = (wid & 3) * 32;
    const int wn = (wid >> 2) * 32;
    const int lrow = lane & 15;
    const int lsel = (lane >> 4) * 8;

    float acc[2][4][4];
    #pragma unroll
    for (int mt = 0; mt < 2; mt++)
        #pragma unroll
        for (int nt = 0; nt < 4; nt++)
            #pragma unroll
            for (int i = 0; i < 4; i++) acc[mt][nt][i] = 0.f;

    #pragma unroll
    for (int k0 = 0; k0 < K; k0 += 16) {
        uint32_t a_hi[2][4], a_lo[2][4];
        #pragma unroll
        for (int mt = 0; mt < 2; mt++) {
            uint32_t off = (uint32_t)((wm + 16 * mt + lrow) * SA_H + k0 + lsel) * 2;
            ldsm_x4(a_hi[mt], sbase + A_HI + off);
            ldsm_x4(a_lo[mt], sbase + A_LO + off);
        }
        uint32_t b_hi[2][4], b_lo[2][4];
        #pragma unroll
        for (int h = 0; h < 2; h++) {
            uint32_t off = (uint32_t)((k0 + lrow) * SB_H + wn + 16 * h + lsel) * 2;
            ldsm_x4_t(b_hi[h], sbase + B_HI + off);
            ldsm_x4_t(b_lo[h], sbase + B_LO + off);
        }
        #pragma unroll
        for (int mt = 0; mt < 2; mt++)
            #pragma unroll
            for (int nt = 0; nt < 4; nt++) {
                const uint32_t* bh = &b_hi[nt >> 1][(nt & 1) * 2];
                const uint32_t* bl = &b_lo[nt >> 1][(nt & 1) * 2];
                mma_bf16(acc[mt][nt], a_hi[mt], bh);
                mma_bf16(acc[mt][nt], a_hi[mt], bl);
                mma_bf16(acc[mt][nt], a_lo[mt], bh);
            }
    }

    const int g  = lane >> 2;
    const int tg = lane & 3;
    #pragma unroll
    for (int mt = 0; mt < 2; mt++)
        #pragma unroll
        for (int rh = 0; rh < 2; rh++) {
            int row = row0 + wm + 16 * mt + g + 8 * rh;
            if (row >= M) continue;
            float di = g_dinv[row];
            #pragma unroll
            for (int nt = 0; nt < 4; nt++) {
                int col = wn + 8 * nt + 2 * tg;
                *(float2*)&C[(size_t)row * 64 + col] =
                    make_float2(acc[mt][nt][2 * rh] * di, acc[mt][nt][2 * rh + 1] * di);
            }
        }
}

// ---------------- CSR gather over pre-scaled h': out = dd*(Σ h'[s] + h'[node]) ----------------
template<bool LAYER1>
__global__ __launch_bounds__(256)
void gather_kernel(const float* __restrict__ h, const float* __restrict__ bias,
                   float* __restrict__ zout)
{
    int node = blockIdx.x * 8 + (threadIdx.x >> 5);   // warp per node
    int lane = threadIdx.x & 31;
    if (node >= N_NODES) return;

    const char* hp = (const char*)h + lane * 8;       // lane-fixed base
    float2 a0 = *(const float2*)(hp + (size_t)node * 256);   // self-loop (h' = h*dinv)
    float2 a1 = make_float2(0.f, 0.f);
    float2 a2 = make_float2(0.f, 0.f);
    float2 a3 = make_float2(0.f, 0.f);

    int e   = __ldg(&g_rowptr[node]);
    int end = __ldg(&g_rowptr[node + 1]);
    for (; e + 3 < end; e += 4) {
        int o0 = __ldg(&g_csr[e]);
        int o1 = __ldg(&g_csr[e + 1]);
        int o2 = __ldg(&g_csr[e + 2]);
        int o3 = __ldg(&g_csr[e + 3]);
        float2 v0 = *(const float2*)(hp + o0);
        float2 v1 = *(const float2*)(hp + o1);
        float2 v2 = *(const float2*)(hp + o2);
        float2 v3 = *(const float2*)(hp + o3);
        a0.x += v0.x; a0.y += v0.y;
        a1.x += v1.x; a1.y += v1.y;
        a2.x += v2.x; a2.y += v2.y;
        a3.x += v3.x; a3.y += v3.y;
    }
    for (; e < end; e++) {
        int o = __ldg(&g_csr[e]);
        float2 v = *(const float2*)(hp + o);
        a0.x += v.x; a0.y += v.y;
    }
    float dd = g_dinv[node];
    float2 acc = make_float2(((a0.x + a1.x) + (a2.x + a3.x)) * dd,
                             ((a0.y + a1.y) + (a2.y + a3.y)) * dd);

    if (LAYER1) {
        float2 b = *(const float2*)&bias[lane * 2];
        float vx = fmaxf(acc.x + b.x, 0.f);
        float vy = fmaxf(acc.y + b.y, 0.f);
        float hx = bf_hi(vx), hy = bf_hi(vy);
        ((uint32_t*)g_z1hi)[node * 32 + lane] = pack_bf16(hx, hy);
        ((uint32_t*)g_z1lo)[node * 32 + lane] = pack_bf16(vx - hx, vy - hy);
    } else {
        *(float2*)&zout[(size_t)node * 64 + lane * 2] = acc;
    }
}

// ---------------- fused decode: ef -> P1+relu -> P2+relu -> P3 dot ----------------
__global__ __launch_bounds__(256)
void decode_kernel(const int* __restrict__ eli, const float* __restrict__ b2,
                   const float* __restrict__ P1, const float* __restrict__ pb1,
                   const float* __restrict__ P2, const float* __restrict__ pb2,
                   const float* __restrict__ P3, const float* __restrict__ pb3,
                   float* __restrict__ out)
{
    constexpr int SA_H = 72, SB_H = 72;
    constexpr int EF_HI = 0;
    constexpr int EF_LO = 128 * SA_H * 2;
    constexpr int P1_HI = 2 * 128 * SA_H * 2;
    constexpr int P1_LO = P1_HI + 64 * SB_H * 2;
    constexpr int P2_HI = P1_LO + 64 * SB_H * 2;
    constexpr int P2_LO = P2_HI + 64 * SB_H * 2;
    constexpr int S_OUT = P2_LO + 64 * SB_H * 2;

    extern __shared__ char smem[];
    const uint32_t sbase = smem_u32(smem);
    const int tid  = threadIdx.x;
    const int wid  = tid >> 5;
    const int lane = tid & 31;
    const int row0 = blockIdx.x * 128;

    if (tid < 128) *(float*)(smem + S_OUT + tid * 4) = 0.f;

    #pragma unroll
    for (int idx = tid; idx < 128 * 16; idx += 256) {
        int pl = idx >> 4, c4 = (idx & 15) << 2;
        int p = row0 + pl;
        float4 r = make_float4(0.f, 0.f, 0.f, 0.f);
        if (p < N_EL) {
            int a = __ldg(&eli[p]);
            int b = __ldg(&eli[N_EL + p]);
            float4 bb = *(const float4*)&b2[c4];
            float4 za = *(const float4*)&g_z2[a * 64 + c4];
            float4 zb = *(const float4*)&g_z2[b * 64 + c4];
            r.x = (za.x + bb.x) * (zb.x + bb.x);
            r.y = (za.y + bb.y) * (zb.y + bb.y);
            r.z = (za.z + bb.z) * (zb.z + bb.z);
            r.w = (za.w + bb.w) * (zb.w + bb.w);
        }
        float hx = bf_hi(r.x), hy = bf_hi(r.y), hz = bf_hi(r.z), hw = bf_hi(r.w);
        uint32_t off = (uint32_t)(pl * SA_H + c4) * 2;
        *(uint2*)(smem + EF_HI + off) = make_uint2(pack_bf16(hx, hy), pack_bf16(hz, hw));
        *(uint2*)(smem + EF_LO + off) = make_uint2(pack_bf16(r.x - hx, r.y - hy),
                                                   pack_bf16(r.z - hz, r.w - hw));
    }
    #pragma unroll
    for (int idx = tid; idx < 64 * 16; idx += 256) {
        int k = idx >> 4, nc = (idx & 15) << 2;
        uint32_t off = (uint32_t)(k * SB_H + nc) * 2;
        float4 v = *(const float4*)&P1[k * 64 + nc];
        float hx = bf_hi(v.x), hy = bf_hi(v.y), hz = bf_hi(v.z), hw = bf_hi(v.w);
        *(uint2*)(smem + P1_HI + off) = make_uint2(pack_bf16(hx, hy), pack_bf16(hz, hw));
        *(uint2*)(smem + P1_LO + off) = make_uint2(pack_bf16(v.x - hx, v.y - hy),
                                                   pack_bf16(v.z - hz, v.w - hw));
        float4 u = *(const float4*)&P2[k * 64 + nc];
        float ux = bf_hi(u.x), uy = bf_hi(u.y), uz = bf_hi(u.z), uw = bf_hi(u.w);
        *(uint2*)(smem + P2_HI + off) = make_uint2(pack_bf16(ux, uy), pack_bf16(uz, uw));
        *(uint2*)(smem + P2_LO + off) = make_uint2(pack_bf16(u.x - ux, u.y - uy),
                                                   pack_bf16(u.z - uz, u.w - uw));
    }
    __syncthreads();

    const int wm = (wid & 3) * 32;
    const int wn = (wid >> 2) * 32;
    const int lrow = lane & 15;
    const int lsel = (lane >> 4) * 8;
    const int g  = lane >> 2;
    const int tg = lane & 3;

    float acc[2][4][4];
    #pragma unroll
    for (int mt = 0; mt < 2; mt++)
        #pragma unroll
        for (int nt = 0; nt < 4; nt++)
            #pragma unroll
            for (int i = 0; i < 4; i++) acc[mt][nt][i] = 0.f;

    #pragma unroll
    for (int k0 = 0; k0 < 64; k0 += 16) {
        uint32_t a_hi[2][4], a_lo[2][4];
        #pragma unroll
        for (int mt = 0; mt < 2; mt++) {
            uint32_t off = (uint32_t)((wm + 16 * mt + lrow) * SA_H + k0 + lsel) * 2;
            ldsm_x4(a_hi[mt], sbase + EF_HI + off);
            ldsm_x4(a_lo[mt], sbase + EF_LO + off);
        }
        uint32_t b_hi[2][4], b_lo[2][4];
        #pragma unroll
        for (int h = 0; h < 2; h++) {
            uint32_t off = (uint32_t)((k0 + lrow) * SB_H + wn + 16 * h + lsel) * 2;
            ldsm_x4_t(b_hi[h], sbase + P1_HI + off);
            ldsm_x4_t(b_lo[h], sbase + P1_LO + off);
        }
        #pragma unroll
        for (int mt = 0; mt < 2; mt++)
            #pragma unroll
            for (int nt = 0; nt < 4; nt++) {
                const uint32_t* bh = &b_hi[nt >> 1][(nt & 1) * 2];
                const uint32_t* bl = &b_lo[nt >> 1][(nt & 1) * 2];
                mma_bf16(acc[mt][nt], a_hi[mt], bh);
                mma_bf16(acc[mt][nt], a_hi[mt], bl);
                mma_bf16(acc[mt][nt], a_lo[mt], bh);
            }
    }
    __syncthreads();

    #pragma unroll
    for (int mt = 0; mt < 2; mt++)
        #pragma unroll
        for (int rh = 0; rh < 2; rh++) {
            int rl = wm + 16 * mt + g + 8 * rh;
            #pragma unroll
            for (int nt = 0; nt < 4; nt++) {
                int col = wn + 8 * nt + 2 * tg;
                float vx = fmaxf(acc[mt][nt][2 * rh]     + __ldg(&pb1[col]),     0.f);
                float vy = fmaxf(acc[mt][nt][2 * rh + 1] + __ldg(&pb1[col + 1]), 0.f);
                float hx = bf_hi(vx), hy = bf_hi(vy);
                uint32_t off = (uint32_t)(rl * SA_H + col) * 2;
                *(uint32_t*)(smem + EF_HI + off) = pack_bf16(hx, hy);
                *(uint32_t*)(smem + EF_LO + off) = pack_bf16(vx - hx, vy - hy);
            }
        }
    __syncthreads();

    #pragma unroll
    for (int mt = 0; mt < 2; mt++)
        #pragma unroll
        for (int nt = 0; nt < 4; nt++)
            #pragma unroll
            for (int i = 0; i < 4; i++) acc[mt][nt][i] = 0.f;

    #pragma unroll
    for (int k0 = 0; k0 < 64; k0 += 16) {
        uint32_t a_hi[2][4], a_lo[2][4];
        #pragma unroll
        for (int mt = 0; mt < 2; mt++) {
            uint32_t off = (uint32_t)((wm + 16 * mt + lrow) * SA_H + k0 + lsel) * 2;
            ldsm_x4(a_hi[mt], sbase + EF_HI + off);
            ldsm_x4(a_lo[mt], sbase + EF_LO + off);
        }
        uint32_t b_hi[2][4], b_lo[2][4];
        #pragma unroll
        for (int h = 0; h < 2; h++) {
            uint32_t off = (uint32_t)((k0 + lrow) * SB_H + wn + 16 * h + lsel) * 2;
            ldsm_x4_t(b_hi[h], sbase + P2_HI + off);
            ldsm_x4_t(b_lo[h], sbase + P2_LO + off);
        }
        #pragma unroll
        for (int mt = 0; mt < 2; mt++)
            #pragma unroll
            for (int nt = 0; nt < 4; nt++) {
                const uint32_t* bh = &b_hi[nt >> 1][(nt & 1) * 2];
                const uint32_t* bl = &b_lo[nt >> 1][(nt & 1) * 2];
                mma_bf16(acc[mt][nt], a_hi[mt], bh);
                mma_bf16(acc[mt][nt], a_hi[mt], bl);
                mma_bf16(acc[mt][nt], a_lo[mt], bh);
            }
    }

    #pragma unroll
    for (int mt = 0; mt < 2; mt++)
        #pragma unroll
        for (int rh = 0; rh < 2; rh++) {
            float s = 0.f;
            #pragma unroll
            for (int nt = 0; nt < 4; nt++) {
                int col = wn + 8 * nt + 2 * tg;
                float vx = fmaxf(acc[mt][nt][2 * rh]     + __ldg(&pb2[col]),     0.f);
                float vy = fmaxf(acc[mt][nt][2 * rh + 1] + __ldg(&pb2[col + 1]), 0.f);
                s += vx * __ldg(&P3[col]) + vy * __ldg(&P3[col + 1]);
            }
            s += __shfl_xor_sync(0xffffffffu, s, 1);
            s += __shfl_xor_sync(0xffffffffu, s, 2);
            if (tg == 0) {
                int rl = wm + 16 * mt + g + 8 * rh;
                atomicAdd((float*)(smem + S_OUT) + rl, s);
            }
        }
    __syncthreads();
    if (tid < 128) {
        int p = row0 + tid;
        if (p < N_EL) out[p] = *(float*)(smem + S_OUT + tid * 4) + __ldg(&pb3[0]);
    }
}

// ---------------- launcher ----------------
extern "C" void kernel_launch(void* const* d_in, const int* in_sizes, int n_in,
                              void* d_out, int out_size)
{
    const float* x   = (const float*)d_in[0];
    const int*   ei  = (const int*)  d_in[1];
    const int*   eli = (const int*)  d_in[2];
    const float* W1  = (const float*)d_in[3];
    const float* b1  = (const float*)d_in[4];
    const float* W2  = (const float*)d_in[5];
    const float* b2  = (const float*)d_in[6];
    const float* P1  = (const float*)d_in[7];
    const float* pb1 = (const float*)d_in[8];
    const float* P2  = (const float*)d_in[9];
    const float* pb2 = (const float*)d_in[10];
    const float* P3  = (const float*)d_in[11];
    const float* pb3 = (const float*)d_in[12];
    float* out = (float*)d_out;

    const int* src = ei;
    const int* dst = ei + N_EDGES;

    float *ph1, *ph2, *pz2;
    cudaGetSymbolAddress((void**)&ph1, g_h1);
    cudaGetSymbolAddress((void**)&ph2, g_h2);
    cudaGetSymbolAddress((void**)&pz2, g_z2);
    __nv_bfloat16 *pxhi, *pxlo, *pz1hi, *pz1lo, *pw1hi, *pw1lo, *pw2hi, *pw2lo;
    cudaGetSymbolAddress((void**)&pxhi,  g_xhi);
    cudaGetSymbolAddress((void**)&pxlo,  g_xlo);
    cudaGetSymbolAddress((void**)&pz1hi, g_z1hi);
    cudaGetSymbolAddress((void**)&pz1lo, g_z1lo);
    cudaGetSymbolAddress((void**)&pw1hi, g_w1hi);
    cudaGetSymbolAddress((void**)&pw1lo, g_w1lo);
    cudaGetSymbolAddress((void**)&pw2hi, g_w2hi);
    cudaGetSymbolAddress((void**)&pw2lo, g_w2lo);

    const int SM128 = 2 * 128 * (128 + 8) * 2 + 2 * 128 * 72 * 2;  // 106496
    const int SM64  = 2 * 128 * (64 + 8) * 2  + 2 * 64 * 72 * 2;   //  55296
    const int SMDEC = 2 * 128 * 72 * 2 + 6 * 64 * 72 * 2 + 512;    //  74240
    cudaFuncSetAttribute(scan_gemm1_kernel, cudaFuncAttributeMaxDynamicSharedMemorySize, SM128);
    cudaFuncSetAttribute(mma_gemm_pre<64>,  cudaFuncAttributeMaxDynamicSharedMemorySize, SM64);
    cudaFuncSetAttribute(decode_kernel,     cudaFuncAttributeMaxDynamicSharedMemorySize, SMDEC);

    const int gbN  = (N_NODES + 127) / 128;   // 391
    const int gbEL = (N_EL    + 127) / 128;   // 782
    const int gbG  = (N_NODES + 7) / 8;       // 6250

    // K1: degree count + operand splits (degi starts at 0 by invariant)
    prep_count_kernel<<<CB + XB + W1B + W2B, 256>>>(dst, x, W1, W2);
    // K2: lookback scan (+dinv) fused with gemm1; epilogue scales by dinv after scan-done
    scan_gemm1_kernel<<<NSCAN_BLOCKS + gbN, 256, SM128>>>(pxhi, pxlo, pw1hi, pw1lo, ph1, N_NODES);
    // K3: CSR fill (byte offsets; restores degi=0, scanstate=0, scandone=0)
    fill_csr_kernel<<<CB, 256>>>(src, dst);
    // gather layer 1 (+bias+relu+split fused)
    gather_kernel<true><<<gbG, 256>>>(ph1, b1, nullptr);
    // conv layer 2 (epilogue scaled by dinv)
    mma_gemm_pre<64><<<gbN, 256, SM64>>>(pz1hi, pz1lo, pw2hi, pw2lo, ph2, N_NODES);
    gather_kernel<false><<<gbG, 256>>>(ph2, nullptr, pz2);
    // fused decode
    decode_kernel<<<gbEL, 256, SMDEC>>>(eli, b2, P1, pb1, P2, pb2, P3, pb3, out);
}